// round 1
// baseline (speedup 1.0000x reference)
#include <cuda_runtime.h>

#define NQ 10000
#define BB 128
#define SS 200
#define DKk 128
#define DVv 64
#define ROWS (BB*SS)   // 25600

// Scratch (static device globals — no allocation)
__device__ float g_w[ROWS*DVv];
__device__ float g_e[ROWS*DKk];
__device__ float g_a[ROWS*DKk];
__device__ float g_reads[ROWS*DKk];

// ---------------------------------------------------------------------------
// Kernel 1: w = softmax(k_emb[q] @ Mk^T)   [25600 x 64]
// grid 400, block 256 (16x16 micro-tiles of 4x4), smem 68608B dynamic
// ---------------------------------------------------------------------------
__global__ void kern_w(const int* __restrict__ qseq,
                       const float* __restrict__ k_emb,
                       const float* __restrict__ Mk) {
    extern __shared__ float sm[];
    float* shA = sm;               // [64][132] row-major, padded
    float* shB = sm + 64 * 132;    // [128][68] Mk transposed, padded
    __shared__ int shq[64];

    const int tid  = threadIdx.x;
    const int tile = blockIdx.x;

    if (tid < 64) shq[tid] = qseq[tile * 64 + tid];
    __syncthreads();

    // Stage A: gather 64 k-rows (each 512B, coalesced float4)
#pragma unroll
    for (int i = 0; i < 8; i++) {
        int idx = tid + i * 256;           // 0..2047
        int r = idx >> 5, kc = idx & 31;
        float4 v = *(const float4*)(k_emb + (size_t)shq[r] * DKk + kc * 4);
        *(float4*)(shA + r * 132 + kc * 4) = v;
    }
    // Stage B: transpose Mk[col][kk] -> shB[kk][col]
#pragma unroll
    for (int i = 0; i < 8; i++) {
        int idx = tid + i * 256;           // 0..2047
        int col = idx & 63, kc = idx >> 6; // kc 0..31
        float4 v = *(const float4*)(Mk + col * DKk + kc * 4);
        shB[(kc * 4 + 0) * 68 + col] = v.x;
        shB[(kc * 4 + 1) * 68 + col] = v.y;
        shB[(kc * 4 + 2) * 68 + col] = v.z;
        shB[(kc * 4 + 3) * 68 + col] = v.w;
    }
    __syncthreads();

    const int ty = tid >> 4, tx = tid & 15;
    const int r0 = ty * 4, c0 = tx * 4;
    float acc[4][4] = {};
#pragma unroll 4
    for (int kk = 0; kk < DKk; kk++) {
        float4 b = *(const float4*)(shB + kk * 68 + c0);
#pragma unroll
        for (int i = 0; i < 4; i++) {
            float a = shA[(r0 + i) * 132 + kk];
            acc[i][0] = fmaf(a, b.x, acc[i][0]);
            acc[i][1] = fmaf(a, b.y, acc[i][1]);
            acc[i][2] = fmaf(a, b.z, acc[i][2]);
            acc[i][3] = fmaf(a, b.w, acc[i][3]);
        }
    }
    // Softmax over 64 cols: each row spread across 16 tx lanes (same half-warp)
#pragma unroll
    for (int i = 0; i < 4; i++) {
        float m = fmaxf(fmaxf(acc[i][0], acc[i][1]), fmaxf(acc[i][2], acc[i][3]));
#pragma unroll
        for (int o = 1; o < 16; o <<= 1)
            m = fmaxf(m, __shfl_xor_sync(0xffffffffu, m, o));
        float e0 = __expf(acc[i][0] - m), e1 = __expf(acc[i][1] - m);
        float e2 = __expf(acc[i][2] - m), e3 = __expf(acc[i][3] - m);
        float s = (e0 + e1) + (e2 + e3);
#pragma unroll
        for (int o = 1; o < 16; o <<= 1)
            s += __shfl_xor_sync(0xffffffffu, s, o);
        float inv = 1.0f / s;
        int row = tile * 64 + r0 + i;
        float4 o4 = make_float4(e0 * inv, e1 * inv, e2 * inv, e3 * inv);
        *(float4*)(g_w + (size_t)row * DVv + c0) = o4;
    }
}

// ---------------------------------------------------------------------------
// Kernel 2: e = sigmoid(v@eW+eb) (y=0) / a = tanh(v@aW+ab) (y=1)
// grid (400,2), block 256, tiles 64x128, smem 99328B
// ---------------------------------------------------------------------------
__global__ void kern_ea(const int* __restrict__ qseq, const int* __restrict__ cseq,
                        const float* __restrict__ v_emb,
                        const float* __restrict__ eW, const float* __restrict__ eb,
                        const float* __restrict__ aW, const float* __restrict__ ab) {
    extern __shared__ float sm[];
    float* shA = sm;              // [64][132]
    float* shB = sm + 64 * 132;   // [128][128]
    __shared__ int shx[64];

    const int tid  = threadIdx.x;
    const int tile = blockIdx.x;
    const int which = blockIdx.y;
    const float* W    = which ? aW : eW;
    const float* bias = which ? ab : eb;
    float* outbuf     = which ? g_a : g_e;

    if (tid < 64) {
        int row = tile * 64 + tid;
        shx[tid] = qseq[row] + NQ * cseq[row];
    }
    __syncthreads();

#pragma unroll
    for (int i = 0; i < 8; i++) {
        int idx = tid + i * 256;
        int r = idx >> 5, kc = idx & 31;
        *(float4*)(shA + r * 132 + kc * 4) =
            *(const float4*)(v_emb + (size_t)shx[r] * DKk + kc * 4);
    }
#pragma unroll
    for (int i = 0; i < 16; i++) {
        int idx = tid + i * 256;   // 4096 float4s = 128x128
        *(float4*)(shB + idx * 4) = *(const float4*)(W + idx * 4);
    }
    __syncthreads();

    const int ty = tid >> 4, tx = tid & 15;
    const int r0 = ty * 4, c0 = tx * 8;
    float acc[4][8] = {};
#pragma unroll 2
    for (int kk = 0; kk < DKk; kk++) {
        float4 b0 = *(const float4*)(shB + kk * DKk + c0);
        float4 b1 = *(const float4*)(shB + kk * DKk + c0 + 4);
#pragma unroll
        for (int i = 0; i < 4; i++) {
            float a = shA[(r0 + i) * 132 + kk];
            acc[i][0] = fmaf(a, b0.x, acc[i][0]);
            acc[i][1] = fmaf(a, b0.y, acc[i][1]);
            acc[i][2] = fmaf(a, b0.z, acc[i][2]);
            acc[i][3] = fmaf(a, b0.w, acc[i][3]);
            acc[i][4] = fmaf(a, b1.x, acc[i][4]);
            acc[i][5] = fmaf(a, b1.y, acc[i][5]);
            acc[i][6] = fmaf(a, b1.z, acc[i][6]);
            acc[i][7] = fmaf(a, b1.w, acc[i][7]);
        }
    }
#pragma unroll
    for (int i = 0; i < 4; i++) {
        int row = tile * 64 + r0 + i;
        float o[8];
#pragma unroll
        for (int j = 0; j < 8; j++) {
            float x = acc[i][j] + __ldg(bias + c0 + j);
            o[j] = which ? tanhf(x) : (1.0f / (1.0f + __expf(-x)));
        }
        *(float4*)(outbuf + (size_t)row * DKk + c0)     = make_float4(o[0], o[1], o[2], o[3]);
        *(float4*)(outbuf + (size_t)row * DKk + c0 + 4) = make_float4(o[4], o[5], o[6], o[7]);
    }
}

// ---------------------------------------------------------------------------
// Kernel 3: sequential scan. One CTA per batch, thread j owns column j,
// M[64] register-resident. read BEFORE update (matches reference).
// ---------------------------------------------------------------------------
__global__ void kern_scan(const float* __restrict__ Mv0) {
    const int b = blockIdx.x, j = threadIdx.x;
    float M[DVv];
#pragma unroll
    for (int v = 0; v < DVv; v++) M[v] = Mv0[v * DKk + j];

    __shared__ float wsh[2][DVv];
    const float* wp = g_w + (size_t)b * SS * DVv;
    const float* ep = g_e + (size_t)b * SS * DKk;
    const float* ap = g_a + (size_t)b * SS * DKk;
    float* rp = g_reads + (size_t)b * SS * DKk;

    for (int s = 0; s < SS; s++) {
        if (j < DVv) wsh[s & 1][j] = wp[s * DVv + j];
        __syncthreads();
        const float e = ep[s * DKk + j];
        const float a = ap[s * DKk + j];
        const float* w = wsh[s & 1];
        float r0 = 0.f, r1 = 0.f, r2 = 0.f, r3 = 0.f;
#pragma unroll
        for (int v = 0; v < DVv; v += 4) {
            float w0 = w[v], w1 = w[v + 1], w2 = w[v + 2], w3 = w[v + 3];
            r0 = fmaf(w0, M[v], r0);
            M[v]     = fmaf(w0, fmaf(-M[v],     e, a), M[v]);
            r1 = fmaf(w1, M[v + 1], r1);
            M[v + 1] = fmaf(w1, fmaf(-M[v + 1], e, a), M[v + 1]);
            r2 = fmaf(w2, M[v + 2], r2);
            M[v + 2] = fmaf(w2, fmaf(-M[v + 2], e, a), M[v + 2]);
            r3 = fmaf(w3, M[v + 3], r3);
            M[v + 3] = fmaf(w3, fmaf(-M[v + 3], e, a), M[v + 3]);
        }
        rp[s * DKk + j] = (r0 + r1) + (r2 + r3);
    }
}

// ---------------------------------------------------------------------------
// Kernel 4: f = tanh([reads,k] @ fW + fb); out = sigmoid(f @ pW + pb)
// grid 400, block 256, smem 198656B
// ---------------------------------------------------------------------------
__global__ void kern_pred(const int* __restrict__ qseq,
                          const float* __restrict__ k_emb,
                          const float* __restrict__ fW, const float* __restrict__ fb,
                          const float* __restrict__ pW, const float* __restrict__ pb,
                          float* __restrict__ out) {
    extern __shared__ float sm[];
    float* shA  = sm;                    // [64][260]  (K=256 padded)
    float* shB  = sm + 64 * 260;         // [256][128]
    float* shfb = shB + 256 * 128;       // [128]
    float* shpW = shfb + 128;            // [128]
    __shared__ int shq[64];

    const int tid = threadIdx.x, tile = blockIdx.x;
    if (tid < 64) shq[tid] = qseq[tile * 64 + tid];
    if (tid < 128) { shfb[tid] = fb[tid]; shpW[tid] = pW[tid]; }
    __syncthreads();

#pragma unroll
    for (int i = 0; i < 16; i++) {
        int idx = tid + i * 256;       // 0..4095 : 64 rows x 64 float4
        int r = idx >> 6, kc = idx & 63;
        float4 v;
        if (kc < 32)
            v = *(const float4*)(g_reads + (size_t)(tile * 64 + r) * DKk + kc * 4);
        else
            v = *(const float4*)(k_emb + (size_t)shq[r] * DKk + (kc - 32) * 4);
        *(float4*)(shA + r * 260 + kc * 4) = v;
    }
#pragma unroll
    for (int i = 0; i < 32; i++) {
        int idx = tid + i * 256;       // 8192 float4 = 256x128
        *(float4*)(shB + idx * 4) = *(const float4*)(fW + idx * 4);
    }
    __syncthreads();

    const int ty = tid >> 4, tx = tid & 15;
    const int r0 = ty * 4, c0 = tx * 8;
    float acc[4][8] = {};
#pragma unroll 2
    for (int kk = 0; kk < 256; kk++) {
        float4 b0 = *(const float4*)(shB + kk * DKk + c0);
        float4 b1 = *(const float4*)(shB + kk * DKk + c0 + 4);
#pragma unroll
        for (int i = 0; i < 4; i++) {
            float a = shA[(r0 + i) * 260 + kk];
            acc[i][0] = fmaf(a, b0.x, acc[i][0]);
            acc[i][1] = fmaf(a, b0.y, acc[i][1]);
            acc[i][2] = fmaf(a, b0.z, acc[i][2]);
            acc[i][3] = fmaf(a, b0.w, acc[i][3]);
            acc[i][4] = fmaf(a, b1.x, acc[i][4]);
            acc[i][5] = fmaf(a, b1.y, acc[i][5]);
            acc[i][6] = fmaf(a, b1.z, acc[i][6]);
            acc[i][7] = fmaf(a, b1.w, acc[i][7]);
        }
    }
    const float pbv = pb[0];
#pragma unroll
    for (int i = 0; i < 4; i++) {
        float p = 0.f;
#pragma unroll
        for (int jj = 0; jj < 8; jj++) {
            float f = tanhf(acc[i][jj] + shfb[c0 + jj]);
            p = fmaf(f, shpW[c0 + jj], p);
        }
#pragma unroll
        for (int o = 1; o < 16; o <<= 1)
            p += __shfl_xor_sync(0xffffffffu, p, o);
        if (tx == 0)
            out[tile * 64 + r0 + i] = 1.0f / (1.0f + __expf(-(p + pbv)));
    }
}

// ---------------------------------------------------------------------------
extern "C" void kernel_launch(void* const* d_in, const int* in_sizes, int n_in,
                              void* d_out, int out_size) {
    (void)in_sizes; (void)n_in; (void)out_size;
    const int*   qseq  = (const int*)d_in[0];
    const int*   cseq  = (const int*)d_in[1];
    const float* k_emb = (const float*)d_in[2];
    const float* v_emb = (const float*)d_in[3];
    const float* Mk    = (const float*)d_in[4];
    const float* Mv0   = (const float*)d_in[5];
    const float* fW    = (const float*)d_in[6];
    const float* fb    = (const float*)d_in[7];
    const float* eW    = (const float*)d_in[8];
    const float* eb    = (const float*)d_in[9];
    const float* aW    = (const float*)d_in[10];
    const float* ab    = (const float*)d_in[11];
    const float* pW    = (const float*)d_in[12];
    const float* pb    = (const float*)d_in[13];
    float* out = (float*)d_out;

    cudaFuncSetAttribute(kern_w,    cudaFuncAttributeMaxDynamicSharedMemorySize, 68608);
    cudaFuncSetAttribute(kern_ea,   cudaFuncAttributeMaxDynamicSharedMemorySize, 99328);
    cudaFuncSetAttribute(kern_pred, cudaFuncAttributeMaxDynamicSharedMemorySize, 198656);

    kern_w  <<<400, 256, 68608>>>(qseq, k_emb, Mk);
    kern_ea <<<dim3(400, 2), 256, 99328>>>(qseq, cseq, v_emb, eW, eb, aW, ab);
    kern_scan<<<128, 128>>>(Mv0);
    kern_pred<<<400, 256, 198656>>>(qseq, k_emb, fW, fb, pW, pb, out);
}

// round 2
// speedup vs baseline: 1.4236x; 1.4236x over previous
#include <cuda_runtime.h>

#define NQ 10000
#define BB 128
#define SS 200
#define DKk 128
#define DVv 64
#define ROWS (BB*SS)     // 25600
#define NTILES (ROWS/64) // 400

typedef unsigned long long u64;

__device__ __forceinline__ u64 pk2(float lo, float hi) {
    u64 r; asm("mov.b64 %0,{%1,%2};" : "=l"(r) : "f"(lo), "f"(hi)); return r;
}
__device__ __forceinline__ float2 up2(u64 a) {
    float2 v; asm("mov.b64 {%0,%1},%2;" : "=f"(v.x), "=f"(v.y) : "l"(a)); return v;
}
__device__ __forceinline__ u64 fma2(u64 a, u64 b, u64 c) {
    u64 d; asm("fma.rn.f32x2 %0,%1,%2,%3;" : "=l"(d) : "l"(a), "l"(b), "l"(c)); return d;
}
__device__ __forceinline__ u64 add2(u64 a, u64 b) {
    u64 d; asm("add.rn.f32x2 %0,%1,%2;" : "=l"(d) : "l"(a), "l"(b)); return d;
}

// Scratch
__device__ float g_w[ROWS*DVv];
__device__ float g_e[ROWS*DKk];
__device__ float g_a[ROWS*DKk];
__device__ float g_reads[ROWS*DKk];

// ---------------------------------------------------------------------------
// Kernel 1: w = softmax(k_emb[q] @ Mk^T).  Persistent: grid 148, 256 thr.
// smem: shA [64][132] + shBt [128][64]  (~66.6KB)
// ---------------------------------------------------------------------------
__global__ __launch_bounds__(256, 1)
void kern_w(const int* __restrict__ qseq,
            const float* __restrict__ k_emb,
            const float* __restrict__ Mk) {
    extern __shared__ float sm[];
    float* shA  = sm;              // [64][132]
    float* shBt = sm + 64 * 132;   // [128][64]  (Mk transposed: [kk][col])
    __shared__ int shq[64];

    const int tid = threadIdx.x;

    // Stage Mk transposed once
#pragma unroll
    for (int i = 0; i < 8; i++) {
        int idx = tid + i * 256;            // 0..2047
        int col = idx & 63, kc = idx >> 6;  // kc 0..31
        float4 v = *(const float4*)(Mk + col * DKk + kc * 4);
        shBt[(kc * 4 + 0) * 64 + col] = v.x;
        shBt[(kc * 4 + 1) * 64 + col] = v.y;
        shBt[(kc * 4 + 2) * 64 + col] = v.z;
        shBt[(kc * 4 + 3) * 64 + col] = v.w;
    }

    const int ty = tid >> 4, tx = tid & 15;
    const int r0 = ty * 4, c0 = tx * 4;

    for (int t = blockIdx.x; t < NTILES; t += gridDim.x) {
        __syncthreads();   // protect shA/shq from previous tile's readers
        if (tid < 64) shq[tid] = qseq[t * 64 + tid];
        __syncthreads();
#pragma unroll
        for (int i = 0; i < 8; i++) {
            int idx = tid + i * 256;
            int r = idx >> 5, kc = idx & 31;
            *(float4*)(shA + r * 132 + kc * 4) =
                *(const float4*)(k_emb + (size_t)shq[r] * DKk + kc * 4);
        }
        __syncthreads();

        u64 acc[4][2] = {};
#pragma unroll 4
        for (int kk = 0; kk < DKk; kk++) {
            ulonglong2 b = *(const ulonglong2*)(shBt + (kk << 6) + c0);
#pragma unroll
            for (int i = 0; i < 4; i++) {
                float av = shA[(r0 + i) * 132 + kk];
                u64 a2 = pk2(av, av);
                acc[i][0] = fma2(a2, b.x, acc[i][0]);
                acc[i][1] = fma2(a2, b.y, acc[i][1]);
            }
        }
        // softmax across 16 tx lanes (4 cols each)
#pragma unroll
        for (int i = 0; i < 4; i++) {
            float2 v0 = up2(acc[i][0]), v1 = up2(acc[i][1]);
            float m = fmaxf(fmaxf(v0.x, v0.y), fmaxf(v1.x, v1.y));
#pragma unroll
            for (int o = 1; o < 16; o <<= 1)
                m = fmaxf(m, __shfl_xor_sync(0xffffffffu, m, o));
            float e0 = __expf(v0.x - m), e1 = __expf(v0.y - m);
            float e2 = __expf(v1.x - m), e3 = __expf(v1.y - m);
            float s = (e0 + e1) + (e2 + e3);
#pragma unroll
            for (int o = 1; o < 16; o <<= 1)
                s += __shfl_xor_sync(0xffffffffu, s, o);
            float inv = 1.0f / s;
            int row = t * 64 + r0 + i;
            *(float4*)(g_w + (size_t)row * DVv + c0) =
                make_float4(e0 * inv, e1 * inv, e2 * inv, e3 * inv);
        }
    }
}

// ---------------------------------------------------------------------------
// Kernel 2: e = sigmoid(v@eW+eb), a = tanh(v@aW+ab), fused (shared A tile).
// Persistent: grid 148, 256 thr. smem: shA[64][132] + eW[128][128] + aW + bias
// ---------------------------------------------------------------------------
__global__ __launch_bounds__(256, 1)
void kern_ea(const int* __restrict__ qseq, const int* __restrict__ cseq,
             const float* __restrict__ v_emb,
             const float* __restrict__ eW, const float* __restrict__ eb,
             const float* __restrict__ aW, const float* __restrict__ ab) {
    extern __shared__ float sm[];
    float* shA  = sm;                    // [64][132]
    float* shE  = sm + 64 * 132;         // [128][128]
    float* shAw = shE + 128 * 128;       // [128][128]
    float* shEb = shAw + 128 * 128;      // [128]
    float* shAb = shEb + 128;            // [128]
    __shared__ int shx[64];

    const int tid = threadIdx.x;

    // Stage weights once
#pragma unroll
    for (int i = 0; i < 16; i++) {
        int idx = tid + i * 256;
        *(float4*)(shE  + idx * 4) = *(const float4*)(eW + idx * 4);
        *(float4*)(shAw + idx * 4) = *(const float4*)(aW + idx * 4);
    }
    if (tid < 128) { shEb[tid] = eb[tid]; shAb[tid] = ab[tid]; }

    const int ty = tid >> 4, tx = tid & 15;
    const int r0 = ty * 4, c0 = tx * 8;

    for (int t = blockIdx.x; t < NTILES; t += gridDim.x) {
        __syncthreads();
        if (tid < 64) {
            int row = t * 64 + tid;
            shx[tid] = qseq[row] + NQ * cseq[row];
        }
        __syncthreads();
#pragma unroll
        for (int i = 0; i < 8; i++) {
            int idx = tid + i * 256;
            int r = idx >> 5, kc = idx & 31;
            *(float4*)(shA + r * 132 + kc * 4) =
                *(const float4*)(v_emb + (size_t)shx[r] * DKk + kc * 4);
        }
        __syncthreads();

        u64 ae[4][4] = {}, aa[4][4] = {};
#pragma unroll 2
        for (int kk = 0; kk < DKk; kk++) {
            ulonglong2 e01 = *(const ulonglong2*)(shE  + (kk << 7) + c0);
            ulonglong2 e23 = *(const ulonglong2*)(shE  + (kk << 7) + c0 + 4);
            ulonglong2 a01 = *(const ulonglong2*)(shAw + (kk << 7) + c0);
            ulonglong2 a23 = *(const ulonglong2*)(shAw + (kk << 7) + c0 + 4);
#pragma unroll
            for (int i = 0; i < 4; i++) {
                float av = shA[(r0 + i) * 132 + kk];
                u64 a2 = pk2(av, av);
                ae[i][0] = fma2(a2, e01.x, ae[i][0]);
                ae[i][1] = fma2(a2, e01.y, ae[i][1]);
                ae[i][2] = fma2(a2, e23.x, ae[i][2]);
                ae[i][3] = fma2(a2, e23.y, ae[i][3]);
                aa[i][0] = fma2(a2, a01.x, aa[i][0]);
                aa[i][1] = fma2(a2, a01.y, aa[i][1]);
                aa[i][2] = fma2(a2, a23.x, aa[i][2]);
                aa[i][3] = fma2(a2, a23.y, aa[i][3]);
            }
        }
#pragma unroll
        for (int i = 0; i < 4; i++) {
            int row = t * 64 + r0 + i;
            float* ge = g_e + (size_t)row * DKk + c0;
            float* ga = g_a + (size_t)row * DKk + c0;
#pragma unroll
            for (int jp = 0; jp < 4; jp++) {
                float2 ve = up2(ae[i][jp]);
                float2 va = up2(aa[i][jp]);
                float2 oe, oa;
                oe.x = 1.0f / (1.0f + __expf(-(ve.x + shEb[c0 + 2*jp])));
                oe.y = 1.0f / (1.0f + __expf(-(ve.y + shEb[c0 + 2*jp + 1])));
                oa.x = tanhf(va.x + shAb[c0 + 2*jp]);
                oa.y = tanhf(va.y + shAb[c0 + 2*jp + 1]);
                *(float2*)(ge + 2*jp) = oe;
                *(float2*)(ga + 2*jp) = oa;
            }
        }
    }
}

// ---------------------------------------------------------------------------
// Kernel 3: sequential scan, f32x2, negated-M/negated-w form, prefetched.
// grid 128 (one per batch), 128 threads (one per column j).
// ---------------------------------------------------------------------------
__global__ __launch_bounds__(128, 1)
void kern_scan(const float* __restrict__ Mv0) {
    const int b = blockIdx.x, j = threadIdx.x;

    u64 Mn[DVv/2];                 // Mn = -M, packed pairs over v
#pragma unroll
    for (int p = 0; p < DVv/2; p++)
        Mn[p] = pk2(-Mv0[(2*p) * DKk + j], -Mv0[(2*p + 1) * DKk + j]);

    __shared__ float wshf[2][DVv];   // negated w, double-buffered
    const float* wp = g_w + (size_t)b * SS * DVv;
    const float* ep = g_e + (size_t)b * SS * DKk;
    const float* ap = g_a + (size_t)b * SS * DKk;
    float* rp = g_reads + (size_t)b * SS * DKk;

    if (j < DVv) wshf[0][j] = -wp[j];
    float e_cur = ep[j], a_cur = ap[j];
    __syncthreads();

    for (int s = 0; s < SS; s++) {
        int sn = (s + 1 < SS) ? s + 1 : s;
        float wnext = (j < DVv) ? wp[sn * DVv + j] : 0.0f;
        float enext = ep[sn * DKk + j];
        float anext = ap[sn * DKk + j];

        u64 e2 = pk2(e_cur, e_cur);
        u64 a2 = pk2(a_cur, a_cur);
        const float* w = wshf[s & 1];
        u64 rA = 0, rB = 0, rC = 0, rD = 0;
#pragma unroll
        for (int p = 0; p < DVv/2; p += 4) {
            u64 w0 = *(const u64*)(w + 2*p);
            u64 w1 = *(const u64*)(w + 2*p + 2);
            u64 w2 = *(const u64*)(w + 2*p + 4);
            u64 w3 = *(const u64*)(w + 2*p + 6);
            rA = fma2(w0, Mn[p],     rA);
            Mn[p]     = fma2(w0, fma2(Mn[p],     e2, a2), Mn[p]);
            rB = fma2(w1, Mn[p + 1], rB);
            Mn[p + 1] = fma2(w1, fma2(Mn[p + 1], e2, a2), Mn[p + 1]);
            rC = fma2(w2, Mn[p + 2], rC);
            Mn[p + 2] = fma2(w2, fma2(Mn[p + 2], e2, a2), Mn[p + 2]);
            rD = fma2(w3, Mn[p + 3], rD);
            Mn[p + 3] = fma2(w3, fma2(Mn[p + 3], e2, a2), Mn[p + 3]);
        }
        // r accumulators hold (-w)*(-M) = +w*M
        float2 fr = up2(add2(add2(rA, rB), add2(rC, rD)));
        rp[s * DKk + j] = fr.x + fr.y;

        if (j < DVv) wshf[(s + 1) & 1][j] = -wnext;
        __syncthreads();
        e_cur = enext; a_cur = anext;
    }
}

// ---------------------------------------------------------------------------
// Kernel 4: f = tanh([reads,k]@fW+fb); out = sigmoid(f@pW+pb).
// Persistent: grid 148, 256 thr. smem: shA[64][260] + fW[256][128] + fb + pW
// ---------------------------------------------------------------------------
__global__ __launch_bounds__(256, 1)
void kern_pred(const int* __restrict__ qseq,
               const float* __restrict__ k_emb,
               const float* __restrict__ fW, const float* __restrict__ fb,
               const float* __restrict__ pW, const float* __restrict__ pb,
               float* __restrict__ out) {
    extern __shared__ float sm[];
    float* shA  = sm;                    // [64][260]
    float* shB  = sm + 64 * 260;         // [256][128]
    float* shfb = shB + 256 * 128;       // [128]
    float* shpW = shfb + 128;            // [128]
    __shared__ int shq[64];

    const int tid = threadIdx.x;

#pragma unroll
    for (int i = 0; i < 32; i++) {
        int idx = tid + i * 256;
        *(float4*)(shB + idx * 4) = *(const float4*)(fW + idx * 4);
    }
    if (tid < 128) { shfb[tid] = fb[tid]; shpW[tid] = pW[tid]; }
    const float pbv = pb[0];

    const int ty = tid >> 4, tx = tid & 15;
    const int r0 = ty * 4, c0 = tx * 8;

    for (int t = blockIdx.x; t < NTILES; t += gridDim.x) {
        __syncthreads();
        if (tid < 64) shq[tid] = qseq[t * 64 + tid];
        __syncthreads();
#pragma unroll
        for (int i = 0; i < 16; i++) {
            int idx = tid + i * 256;        // 64 rows x 64 float4
            int r = idx >> 6, kc = idx & 63;
            float4 v;
            if (kc < 32)
                v = *(const float4*)(g_reads + (size_t)(t * 64 + r) * DKk + kc * 4);
            else
                v = *(const float4*)(k_emb + (size_t)shq[r] * DKk + (kc - 32) * 4);
            *(float4*)(shA + r * 260 + kc * 4) = v;
        }
        __syncthreads();

        u64 acc[4][4] = {};
#pragma unroll 2
        for (int kk = 0; kk < 256; kk++) {
            ulonglong2 b01 = *(const ulonglong2*)(shB + (kk << 7) + c0);
            ulonglong2 b23 = *(const ulonglong2*)(shB + (kk << 7) + c0 + 4);
#pragma unroll
            for (int i = 0; i < 4; i++) {
                float av = shA[(r0 + i) * 260 + kk];
                u64 a2 = pk2(av, av);
                acc[i][0] = fma2(a2, b01.x, acc[i][0]);
                acc[i][1] = fma2(a2, b01.y, acc[i][1]);
                acc[i][2] = fma2(a2, b23.x, acc[i][2]);
                acc[i][3] = fma2(a2, b23.y, acc[i][3]);
            }
        }
#pragma unroll
        for (int i = 0; i < 4; i++) {
            float p = 0.0f;
#pragma unroll
            for (int jp = 0; jp < 4; jp++) {
                float2 v = up2(acc[i][jp]);
                float f0 = tanhf(v.x + shfb[c0 + 2*jp]);
                float f1 = tanhf(v.y + shfb[c0 + 2*jp + 1]);
                p = fmaf(f0, shpW[c0 + 2*jp], p);
                p = fmaf(f1, shpW[c0 + 2*jp + 1], p);
            }
#pragma unroll
            for (int o = 1; o < 16; o <<= 1)
                p += __shfl_xor_sync(0xffffffffu, p, o);
            if (tx == 0)
                out[t * 64 + r0 + i] = 1.0f / (1.0f + __expf(-(p + pbv)));
        }
    }
}

// ---------------------------------------------------------------------------
extern "C" void kernel_launch(void* const* d_in, const int* in_sizes, int n_in,
                              void* d_out, int out_size) {
    (void)in_sizes; (void)n_in; (void)out_size;
    const int*   qseq  = (const int*)d_in[0];
    const int*   cseq  = (const int*)d_in[1];
    const float* k_emb = (const float*)d_in[2];
    const float* v_emb = (const float*)d_in[3];
    const float* Mk    = (const float*)d_in[4];
    const float* Mv0   = (const float*)d_in[5];
    const float* fW    = (const float*)d_in[6];
    const float* fb    = (const float*)d_in[7];
    const float* eW    = (const float*)d_in[8];
    const float* eb    = (const float*)d_in[9];
    const float* aW    = (const float*)d_in[10];
    const float* ab    = (const float*)d_in[11];
    const float* pW    = (const float*)d_in[12];
    const float* pb    = (const float*)d_in[13];
    float* out = (float*)d_out;

    const int smw  = (64*132 + 128*64) * 4;                    // 66.6KB
    const int smea = (64*132 + 2*128*128 + 256) * 4;           // 165.9KB
    const int smp  = (64*260 + 256*128 + 256) * 4;             // 198.7KB

    cudaFuncSetAttribute(kern_w,    cudaFuncAttributeMaxDynamicSharedMemorySize, smw);
    cudaFuncSetAttribute(kern_ea,   cudaFuncAttributeMaxDynamicSharedMemorySize, smea);
    cudaFuncSetAttribute(kern_pred, cudaFuncAttributeMaxDynamicSharedMemorySize, smp);

    kern_w   <<<148, 256, smw>>>(qseq, k_emb, Mk);
    kern_ea  <<<148, 256, smea>>>(qseq, cseq, v_emb, eW, eb, aW, ab);
    kern_scan<<<128, 128>>>(Mv0);
    kern_pred<<<148, 256, smp>>>(qseq, k_emb, fW, fb, pW, pb, out);
}

// round 4
// speedup vs baseline: 1.8310x; 1.2862x over previous
#include <cuda_runtime.h>

#define NQ 10000
#define BB 128
#define SS 200
#define DKk 128
#define DVv 64
#define ROWS (BB*SS)     // 25600

typedef unsigned long long u64;

__device__ __forceinline__ u64 pk2(float lo, float hi) {
    u64 r; asm("mov.b64 %0,{%1,%2};" : "=l"(r) : "f"(lo), "f"(hi)); return r;
}
__device__ __forceinline__ float2 up2(u64 a) {
    float2 v; asm("mov.b64 {%0,%1},%2;" : "=f"(v.x), "=f"(v.y) : "l"(a)); return v;
}
__device__ __forceinline__ u64 fma2(u64 a, u64 b, u64 c) {
    u64 d; asm("fma.rn.f32x2 %0,%1,%2,%3;" : "=l"(d) : "l"(a), "l"(b), "l"(c)); return d;
}
__device__ __forceinline__ u64 add2(u64 a, u64 b) {
    u64 d; asm("add.rn.f32x2 %0,%1,%2;" : "=l"(d) : "l"(a), "l"(b)); return d;
}
__device__ __forceinline__ float tanha(float x) {
    float y; asm("tanh.approx.f32 %0,%1;" : "=f"(y) : "f"(x)); return y;
}

// Scratch
__device__ float g_w[ROWS*DVv];
__device__ float g_e[ROWS*DKk];
__device__ float g_a[ROWS*DKk];
__device__ float g_reads[ROWS*DKk];

// ---------------------------------------------------------------------------
// Kernel 1: w = softmax(k_emb[q] @ Mk^T). Persistent, tiles of 128 rows.
// smem: shAT[128][132] (A^T) + shBt[128][68] (Mk^T) = 100KB
// thread: ty=tid>>4 (rows ty*8..+7), tx=tid&15 (cols tx*4..+3)
// ---------------------------------------------------------------------------
__global__ __launch_bounds__(256, 1)
void kern_w(const int* __restrict__ qseq,
            const float* __restrict__ k_emb,
            const float* __restrict__ Mk) {
    extern __shared__ float sm[];
    float* shAT = sm;               // [kk 128][row 132]
    float* shBt = sm + 128 * 132;   // [kk 128][col 68]
    __shared__ int shq[128];

    const int tid = threadIdx.x;

    // Stage Mk transposed once: Mk[col][kk] -> shBt[kk][col]
#pragma unroll
    for (int i = 0; i < 8; i++) {
        int idx = tid + i * 256;            // 0..2047 = 64 cols x 32 kc4
        int col = idx & 63, kc4 = idx >> 6;
        float4 v = *(const float4*)(Mk + col * DKk + kc4 * 4);
        shBt[(kc4 * 4 + 0) * 68 + col] = v.x;
        shBt[(kc4 * 4 + 1) * 68 + col] = v.y;
        shBt[(kc4 * 4 + 2) * 68 + col] = v.z;
        shBt[(kc4 * 4 + 3) * 68 + col] = v.w;
    }

    const int ty = tid >> 4, tx = tid & 15;
    const int rowb = ty * 8, c0 = tx * 4;

    for (int t = blockIdx.x; t < ROWS / 128; t += gridDim.x) {
        __syncthreads();
        if (tid < 128) shq[tid] = qseq[t * 128 + tid];
        __syncthreads();
#pragma unroll
        for (int i = 0; i < 16; i++) {
            int idx = tid + i * 256;        // 0..4095 = 128 rows x 32 kc4
            int r = idx & 127, kc4 = idx >> 7;
            float4 v = *(const float4*)(k_emb + (size_t)shq[r] * DKk + kc4 * 4);
            shAT[(kc4 * 4 + 0) * 132 + r] = v.x;
            shAT[(kc4 * 4 + 1) * 132 + r] = v.y;
            shAT[(kc4 * 4 + 2) * 132 + r] = v.z;
            shAT[(kc4 * 4 + 3) * 132 + r] = v.w;
        }
        __syncthreads();

        u64 acc[4][4] = {};
#pragma unroll 4
        for (int kk = 0; kk < DKk; kk++) {
            ulonglong2 aA = *(const ulonglong2*)(shAT + kk * 132 + rowb);
            ulonglong2 aB = *(const ulonglong2*)(shAT + kk * 132 + rowb + 4);
            float4 bf = *(const float4*)(shBt + kk * 68 + c0);
            u64 b0 = pk2(bf.x, bf.x), b1 = pk2(bf.y, bf.y);
            u64 b2 = pk2(bf.z, bf.z), b3 = pk2(bf.w, bf.w);
            acc[0][0] = fma2(aA.x, b0, acc[0][0]);
            acc[0][1] = fma2(aA.x, b1, acc[0][1]);
            acc[0][2] = fma2(aA.x, b2, acc[0][2]);
            acc[0][3] = fma2(aA.x, b3, acc[0][3]);
            acc[1][0] = fma2(aA.y, b0, acc[1][0]);
            acc[1][1] = fma2(aA.y, b1, acc[1][1]);
            acc[1][2] = fma2(aA.y, b2, acc[1][2]);
            acc[1][3] = fma2(aA.y, b3, acc[1][3]);
            acc[2][0] = fma2(aB.x, b0, acc[2][0]);
            acc[2][1] = fma2(aB.x, b1, acc[2][1]);
            acc[2][2] = fma2(aB.x, b2, acc[2][2]);
            acc[2][3] = fma2(aB.x, b3, acc[2][3]);
            acc[3][0] = fma2(aB.y, b0, acc[3][0]);
            acc[3][1] = fma2(aB.y, b1, acc[3][1]);
            acc[3][2] = fma2(aB.y, b2, acc[3][2]);
            acc[3][3] = fma2(aB.y, b3, acc[3][3]);
        }
        // softmax: rows rowb+2p (lo) and rowb+2p+1 (hi), 64 cols across 16 tx
#pragma unroll
        for (int p = 0; p < 4; p++) {
            float2 v0 = up2(acc[p][0]), v1 = up2(acc[p][1]);
            float2 v2 = up2(acc[p][2]), v3 = up2(acc[p][3]);
            // lo row
            {
                float m = fmaxf(fmaxf(v0.x, v1.x), fmaxf(v2.x, v3.x));
#pragma unroll
                for (int o = 1; o < 16; o <<= 1)
                    m = fmaxf(m, __shfl_xor_sync(0xffffffffu, m, o));
                float e0 = __expf(v0.x - m), e1 = __expf(v1.x - m);
                float e2 = __expf(v2.x - m), e3 = __expf(v3.x - m);
                float s = (e0 + e1) + (e2 + e3);
#pragma unroll
                for (int o = 1; o < 16; o <<= 1)
                    s += __shfl_xor_sync(0xffffffffu, s, o);
                float inv = 1.0f / s;
                int row = t * 128 + rowb + 2 * p;
                *(float4*)(g_w + (size_t)row * DVv + c0) =
                    make_float4(e0 * inv, e1 * inv, e2 * inv, e3 * inv);
            }
            // hi row
            {
                float m = fmaxf(fmaxf(v0.y, v1.y), fmaxf(v2.y, v3.y));
#pragma unroll
                for (int o = 1; o < 16; o <<= 1)
                    m = fmaxf(m, __shfl_xor_sync(0xffffffffu, m, o));
                float e0 = __expf(v0.y - m), e1 = __expf(v1.y - m);
                float e2 = __expf(v2.y - m), e3 = __expf(v3.y - m);
                float s = (e0 + e1) + (e2 + e3);
#pragma unroll
                for (int o = 1; o < 16; o <<= 1)
                    s += __shfl_xor_sync(0xffffffffu, s, o);
                float inv = 1.0f / s;
                int row = t * 128 + rowb + 2 * p + 1;
                *(float4*)(g_w + (size_t)row * DVv + c0) =
                    make_float4(e0 * inv, e1 * inv, e2 * inv, e3 * inv);
            }
        }
    }
}

// ---------------------------------------------------------------------------
// Kernel 2: e = sigmoid(v@eW+eb), a = tanh(v@aW+ab), fused. Tiles of 64 rows.
// smem: shAT[128][68] + shE[128][128] + shAw[128][128] + biases = 163KB
// thread: ty=tid>>5 (rows ty*8..+7), tx=tid&31 (cols tx*4..+3)
// ---------------------------------------------------------------------------
__global__ __launch_bounds__(256, 1)
void kern_ea(const int* __restrict__ qseq, const int* __restrict__ cseq,
             const float* __restrict__ v_emb,
             const float* __restrict__ eW, const float* __restrict__ eb,
             const float* __restrict__ aW, const float* __restrict__ ab) {
    extern __shared__ float sm[];
    float* shAT = sm;                    // [128][68]
    float* shE  = sm + 128 * 68;         // [128][128]
    float* shAw = shE + 128 * 128;       // [128][128]
    float* shEb = shAw + 128 * 128;      // [128]
    float* shAb = shEb + 128;            // [128]
    __shared__ int shx[64];

    const int tid = threadIdx.x;

#pragma unroll
    for (int i = 0; i < 16; i++) {
        int idx = tid + i * 256;
        *(float4*)(shE  + idx * 4) = *(const float4*)(eW + idx * 4);
        *(float4*)(shAw + idx * 4) = *(const float4*)(aW + idx * 4);
    }
    if (tid < 128) { shEb[tid] = eb[tid]; shAb[tid] = ab[tid]; }

    const int ty = tid >> 5, tx = tid & 31;
    const int rowb = ty * 8, c0 = tx * 4;

    for (int t = blockIdx.x; t < ROWS / 64; t += gridDim.x) {
        __syncthreads();
        if (tid < 64) {
            int row = t * 64 + tid;
            shx[tid] = qseq[row] + NQ * cseq[row];
        }
        __syncthreads();
#pragma unroll
        for (int i = 0; i < 8; i++) {
            int idx = tid + i * 256;        // 0..2047 = 64 rows x 32 kc4
            int r = idx & 63, kc4 = idx >> 6;
            float4 v = *(const float4*)(v_emb + (size_t)shx[r] * DKk + kc4 * 4);
            shAT[(kc4 * 4 + 0) * 68 + r] = v.x;
            shAT[(kc4 * 4 + 1) * 68 + r] = v.y;
            shAT[(kc4 * 4 + 2) * 68 + r] = v.z;
            shAT[(kc4 * 4 + 3) * 68 + r] = v.w;
        }
        __syncthreads();

        u64 ace[4][4] = {}, aca[4][4] = {};
#pragma unroll 2
        for (int kk = 0; kk < DKk; kk++) {
            ulonglong2 aA = *(const ulonglong2*)(shAT + kk * 68 + rowb);
            ulonglong2 aB = *(const ulonglong2*)(shAT + kk * 68 + rowb + 4);
            float4 be = *(const float4*)(shE  + (kk << 7) + c0);
            float4 ba = *(const float4*)(shAw + (kk << 7) + c0);
            u64 e0 = pk2(be.x, be.x), e1 = pk2(be.y, be.y);
            u64 e2 = pk2(be.z, be.z), e3 = pk2(be.w, be.w);
            u64 a0 = pk2(ba.x, ba.x), a1 = pk2(ba.y, ba.y);
            u64 a2 = pk2(ba.z, ba.z), a3 = pk2(ba.w, ba.w);
            u64 ap[4] = {aA.x, aA.y, aB.x, aB.y};
#pragma unroll
            for (int p = 0; p < 4; p++) {
                ace[p][0] = fma2(ap[p], e0, ace[p][0]);
                ace[p][1] = fma2(ap[p], e1, ace[p][1]);
                ace[p][2] = fma2(ap[p], e2, ace[p][2]);
                ace[p][3] = fma2(ap[p], e3, ace[p][3]);
                aca[p][0] = fma2(ap[p], a0, aca[p][0]);
                aca[p][1] = fma2(ap[p], a1, aca[p][1]);
                aca[p][2] = fma2(ap[p], a2, aca[p][2]);
                aca[p][3] = fma2(ap[p], a3, aca[p][3]);
            }
        }
        float eb0 = shEb[c0], eb1 = shEb[c0+1], eb2 = shEb[c0+2], eb3 = shEb[c0+3];
        float ab0 = shAb[c0], ab1 = shAb[c0+1], ab2 = shAb[c0+2], ab3 = shAb[c0+3];
#pragma unroll
        for (int p = 0; p < 4; p++) {
            float2 e0 = up2(ace[p][0]), e1 = up2(ace[p][1]);
            float2 e2 = up2(ace[p][2]), e3 = up2(ace[p][3]);
            float2 a0 = up2(aca[p][0]), a1 = up2(aca[p][1]);
            float2 a2 = up2(aca[p][2]), a3 = up2(aca[p][3]);
            int rlo = t * 64 + rowb + 2 * p;
            // lo row
            *(float4*)(g_e + (size_t)rlo * DKk + c0) = make_float4(
                1.0f/(1.0f+__expf(-(e0.x+eb0))), 1.0f/(1.0f+__expf(-(e1.x+eb1))),
                1.0f/(1.0f+__expf(-(e2.x+eb2))), 1.0f/(1.0f+__expf(-(e3.x+eb3))));
            *(float4*)(g_a + (size_t)rlo * DKk + c0) = make_float4(
                tanhf(a0.x+ab0), tanhf(a1.x+ab1), tanhf(a2.x+ab2), tanhf(a3.x+ab3));
            // hi row
            *(float4*)(g_e + (size_t)(rlo+1) * DKk + c0) = make_float4(
                1.0f/(1.0f+__expf(-(e0.y+eb0))), 1.0f/(1.0f+__expf(-(e1.y+eb1))),
                1.0f/(1.0f+__expf(-(e2.y+eb2))), 1.0f/(1.0f+__expf(-(e3.y+eb3))));
            *(float4*)(g_a + (size_t)(rlo+1) * DKk + c0) = make_float4(
                tanhf(a0.y+ab0), tanhf(a1.y+ab1), tanhf(a2.y+ab2), tanhf(a3.y+ab3));
        }
    }
}

// ---------------------------------------------------------------------------
// Kernel 3: sequential scan (fma-throughput bound)
// ---------------------------------------------------------------------------
__global__ __launch_bounds__(128, 1)
void kern_scan(const float* __restrict__ Mv0) {
    const int b = blockIdx.x, j = threadIdx.x;

    u64 Mn[DVv/2];
#pragma unroll
    for (int p = 0; p < DVv/2; p++)
        Mn[p] = pk2(-Mv0[(2*p) * DKk + j], -Mv0[(2*p + 1) * DKk + j]);

    __shared__ float wshf[2][DVv];
    const float* wp = g_w + (size_t)b * SS * DVv;
    const float* ep = g_e + (size_t)b * SS * DKk;
    const float* ap = g_a + (size_t)b * SS * DKk;
    float* rp = g_reads + (size_t)b * SS * DKk;

    if (j < DVv) wshf[0][j] = -wp[j];
    float e_cur = ep[j], a_cur = ap[j];
    __syncthreads();

    for (int s = 0; s < SS; s++) {
        int sn = (s + 1 < SS) ? s + 1 : s;
        float wnext = (j < DVv) ? wp[sn * DVv + j] : 0.0f;
        float enext = ep[sn * DKk + j];
        float anext = ap[sn * DKk + j];

        u64 e2 = pk2(e_cur, e_cur);
        u64 a2 = pk2(a_cur, a_cur);
        const float* w = wshf[s & 1];
        u64 rA = 0, rB = 0, rC = 0, rD = 0;
#pragma unroll
        for (int p = 0; p < DVv/2; p += 4) {
            u64 w0 = *(const u64*)(w + 2*p);
            u64 w1 = *(const u64*)(w + 2*p + 2);
            u64 w2 = *(const u64*)(w + 2*p + 4);
            u64 w3 = *(const u64*)(w + 2*p + 6);
            rA = fma2(w0, Mn[p],     rA);
            Mn[p]     = fma2(w0, fma2(Mn[p],     e2, a2), Mn[p]);
            rB = fma2(w1, Mn[p + 1], rB);
            Mn[p + 1] = fma2(w1, fma2(Mn[p + 1], e2, a2), Mn[p + 1]);
            rC = fma2(w2, Mn[p + 2], rC);
            Mn[p + 2] = fma2(w2, fma2(Mn[p + 2], e2, a2), Mn[p + 2]);
            rD = fma2(w3, Mn[p + 3], rD);
            Mn[p + 3] = fma2(w3, fma2(Mn[p + 3], e2, a2), Mn[p + 3]);
        }
        float2 fr = up2(add2(add2(rA, rB), add2(rC, rD)));
        rp[s * DKk + j] = fr.x + fr.y;

        if (j < DVv) wshf[(s + 1) & 1][j] = -wnext;
        __syncthreads();
        e_cur = enext; a_cur = anext;
    }
}

// ---------------------------------------------------------------------------
// Kernel 4: f = tanh([reads,k]@fW+fb); out = sigmoid(f@pW+pb). Tiles of 64 rows.
// smem: shAT[256][68] + shB[256][128] + fb + pW = 197KB
// thread: ty=tid>>5 (rows ty*8..+7), tx=tid&31 (cols tx*4..+3)
// ---------------------------------------------------------------------------
__global__ __launch_bounds__(256, 1)
void kern_pred(const int* __restrict__ qseq,
               const float* __restrict__ k_emb,
               const float* __restrict__ fW, const float* __restrict__ fb,
               const float* __restrict__ pW, const float* __restrict__ pb,
               float* __restrict__ out) {
    extern __shared__ float sm[];
    float* shAT = sm;                    // [256][68]
    float* shB  = sm + 256 * 68;         // [256][128]
    float* shfb = shB + 256 * 128;       // [128]
    float* shpW = shfb + 128;            // [128]
    __shared__ int shq[64];

    const int tid = threadIdx.x;

#pragma unroll
    for (int i = 0; i < 32; i++) {
        int idx = tid + i * 256;
        *(float4*)(shB + idx * 4) = *(const float4*)(fW + idx * 4);
    }
    if (tid < 128) { shfb[tid] = fb[tid]; shpW[tid] = pW[tid]; }
    const float pbv = pb[0];

    const int ty = tid >> 5, tx = tid & 31;
    const int rowb = ty * 8, c0 = tx * 4;

    for (int t = blockIdx.x; t < ROWS / 64; t += gridDim.x) {
        __syncthreads();
        if (tid < 64) shq[tid] = qseq[t * 64 + tid];
        __syncthreads();
#pragma unroll
        for (int i = 0; i < 16; i++) {
            int idx = tid + i * 256;        // 0..4095 = 64 rows x 64 kc4
            int r = idx & 63, kc4 = idx >> 6;
            float4 v;
            if (kc4 < 32)
                v = *(const float4*)(g_reads + (size_t)(t * 64 + r) * DKk + kc4 * 4);
            else
                v = *(const float4*)(k_emb + (size_t)shq[r] * DKk + (kc4 - 32) * 4);
            shAT[(kc4 * 4 + 0) * 68 + r] = v.x;
            shAT[(kc4 * 4 + 1) * 68 + r] = v.y;
            shAT[(kc4 * 4 + 2) * 68 + r] = v.z;
            shAT[(kc4 * 4 + 3) * 68 + r] = v.w;
        }
        __syncthreads();

        u64 acc[4][4] = {};
#pragma unroll 4
        for (int kk = 0; kk < 256; kk++) {
            ulonglong2 aA = *(const ulonglong2*)(shAT + kk * 68 + rowb);
            ulonglong2 aB = *(const ulonglong2*)(shAT + kk * 68 + rowb + 4);
            float4 bf = *(const float4*)(shB + (kk << 7) + c0);
            u64 b0 = pk2(bf.x, bf.x), b1 = pk2(bf.y, bf.y);
            u64 b2 = pk2(bf.z, bf.z), b3 = pk2(bf.w, bf.w);
            acc[0][0] = fma2(aA.x, b0, acc[0][0]);
            acc[0][1] = fma2(aA.x, b1, acc[0][1]);
            acc[0][2] = fma2(aA.x, b2, acc[0][2]);
            acc[0][3] = fma2(aA.x, b3, acc[0][3]);
            acc[1][0] = fma2(aA.y, b0, acc[1][0]);
            acc[1][1] = fma2(aA.y, b1, acc[1][1]);
            acc[1][2] = fma2(aA.y, b2, acc[1][2]);
            acc[1][3] = fma2(aA.y, b3, acc[1][3]);
            acc[2][0] = fma2(aB.x, b0, acc[2][0]);
            acc[2][1] = fma2(aB.x, b1, acc[2][1]);
            acc[2][2] = fma2(aB.x, b2, acc[2][2]);
            acc[2][3] = fma2(aB.x, b3, acc[2][3]);
            acc[3][0] = fma2(aB.y, b0, acc[3][0]);
            acc[3][1] = fma2(aB.y, b1, acc[3][1]);
            acc[3][2] = fma2(aB.y, b2, acc[3][2]);
            acc[3][3] = fma2(aB.y, b3, acc[3][3]);
        }
        float fb0 = shfb[c0], fb1 = shfb[c0+1], fb2 = shfb[c0+2], fb3 = shfb[c0+3];
        float pw0 = shpW[c0], pw1 = shpW[c0+1], pw2 = shpW[c0+2], pw3 = shpW[c0+3];
#pragma unroll
        for (int p = 0; p < 4; p++) {
            float2 v0 = up2(acc[p][0]), v1 = up2(acc[p][1]);
            float2 v2 = up2(acc[p][2]), v3 = up2(acc[p][3]);
            // lo row
            float plo = tanha(v0.x + fb0) * pw0;
            plo = fmaf(tanha(v1.x + fb1), pw1, plo);
            plo = fmaf(tanha(v2.x + fb2), pw2, plo);
            plo = fmaf(tanha(v3.x + fb3), pw3, plo);
            // hi row
            float phi = tanha(v0.y + fb0) * pw0;
            phi = fmaf(tanha(v1.y + fb1), pw1, phi);
            phi = fmaf(tanha(v2.y + fb2), pw2, phi);
            phi = fmaf(tanha(v3.y + fb3), pw3, phi);
#pragma unroll
            for (int o = 1; o < 32; o <<= 1) {
                plo += __shfl_xor_sync(0xffffffffu, plo, o);
                phi += __shfl_xor_sync(0xffffffffu, phi, o);
            }
            if (tx == 0) {
                int rlo = t * 64 + rowb + 2 * p;
                out[rlo]     = 1.0f / (1.0f + __expf(-(plo + pbv)));
                out[rlo + 1] = 1.0f / (1.0f + __expf(-(phi + pbv)));
            }
        }
    }
}

// ---------------------------------------------------------------------------
extern "C" void kernel_launch(void* const* d_in, const int* in_sizes, int n_in,
                              void* d_out, int out_size) {
    (void)in_sizes; (void)n_in; (void)out_size;
    const int*   qseq  = (const int*)d_in[0];
    const int*   cseq  = (const int*)d_in[1];
    const float* k_emb = (const float*)d_in[2];
    const float* v_emb = (const float*)d_in[3];
    const float* Mk    = (const float*)d_in[4];
    const float* Mv0   = (const float*)d_in[5];
    const float* fW    = (const float*)d_in[6];
    const float* fb    = (const float*)d_in[7];
    const float* eW    = (const float*)d_in[8];
    const float* eb    = (const float*)d_in[9];
    const float* aW    = (const float*)d_in[10];
    const float* ab    = (const float*)d_in[11];
    const float* pW    = (const float*)d_in[12];
    const float* pb    = (const float*)d_in[13];
    float* out = (float*)d_out;

    const int smw  = (128*132 + 128*68) * 4;                   // 102400
    const int smea = (128*68 + 2*128*128 + 256) * 4;           // 166912
    const int smp  = (256*68 + 256*128 + 256) * 4;             // 201728

    cudaFuncSetAttribute(kern_w,    cudaFuncAttributeMaxDynamicSharedMemorySize, smw);
    cudaFuncSetAttribute(kern_ea,   cudaFuncAttributeMaxDynamicSharedMemorySize, smea);
    cudaFuncSetAttribute(kern_pred, cudaFuncAttributeMaxDynamicSharedMemorySize, smp);

    kern_w   <<<148, 256, smw>>>(qseq, k_emb, Mk);
    kern_ea  <<<148, 256, smea>>>(qseq, cseq, v_emb, eW, eb, aW, ab);
    kern_scan<<<128, 128>>>(Mv0);
    kern_pred<<<148, 256, smp>>>(qseq, k_emb, fW, fb, pW, pb, out);
}

// round 5
// speedup vs baseline: 1.8330x; 1.0011x over previous
#include <cuda_runtime.h>

#define NQ 10000
#define BB 128
#define SS 200
#define DKk 128
#define DVv 64
#define ROWS (BB*SS)     // 25600

typedef unsigned long long u64;

__device__ __forceinline__ u64 pk2(float lo, float hi) {
    u64 r; asm("mov.b64 %0,{%1,%2};" : "=l"(r) : "f"(lo), "f"(hi)); return r;
}
__device__ __forceinline__ float2 up2(u64 a) {
    float2 v; asm("mov.b64 {%0,%1},%2;" : "=f"(v.x), "=f"(v.y) : "l"(a)); return v;
}
__device__ __forceinline__ u64 fma2(u64 a, u64 b, u64 c) {
    u64 d; asm("fma.rn.f32x2 %0,%1,%2,%3;" : "=l"(d) : "l"(a), "l"(b), "l"(c)); return d;
}
__device__ __forceinline__ u64 add2(u64 a, u64 b) {
    u64 d; asm("add.rn.f32x2 %0,%1,%2;" : "=l"(d) : "l"(a), "l"(b)); return d;
}
__device__ __forceinline__ float tanha(float x) {
    float y; asm("tanh.approx.f32 %0,%1;" : "=f"(y) : "f"(x)); return y;
}

// Scratch
__device__ float g_w[ROWS*DVv];
__device__ float g_e[ROWS*DKk];
__device__ float g_a[ROWS*DKk];
__device__ float g_reads[ROWS*DKk];

// ---------------------------------------------------------------------------
// Kernel 1: w = softmax(k_emb[q] @ Mk^T). 512 thr, 64-row tiles (400 tiles).
// smem: shAT[128 kk][68] + shBt[128 kk][68] = 69.6KB
// warp covers 4 rows x 64 cols: rowb = wid*4 + (lane>>4)*2, c0 = (lane&15)*4
// ---------------------------------------------------------------------------
__global__ __launch_bounds__(512, 1)
void kern_w(const int* __restrict__ qseq,
            const float* __restrict__ k_emb,
            const float* __restrict__ Mk) {
    extern __shared__ float sm[];
    float* shAT = sm;               // [kk 128][row 68]
    float* shBt = sm + 128 * 68;    // [kk 128][col 68]
    __shared__ int shq[64];

    const int tid = threadIdx.x;
    const int lane = tid & 31;
    const int wid  = tid >> 5;

    // Stage Mk transposed once: Mk[col][kk] -> shBt[kk][col]
#pragma unroll
    for (int i = 0; i < 4; i++) {
        int idx = tid + i * 512;            // 0..2047 = 64 cols x 32 kc4
        int col = idx & 63, kc4 = idx >> 6;
        float4 v = *(const float4*)(Mk + col * DKk + kc4 * 4);
        shBt[(kc4 * 4 + 0) * 68 + col] = v.x;
        shBt[(kc4 * 4 + 1) * 68 + col] = v.y;
        shBt[(kc4 * 4 + 2) * 68 + col] = v.z;
        shBt[(kc4 * 4 + 3) * 68 + col] = v.w;
    }

    const int rowb = wid * 4 + (lane >> 4) * 2;  // 2 rows per thread
    const int c0   = (lane & 15) * 4;            // 4 cols per thread

    for (int t = blockIdx.x; t < ROWS / 64; t += gridDim.x) {
        __syncthreads();
        if (tid < 64) shq[tid] = qseq[t * 64 + tid];
        __syncthreads();
#pragma unroll
        for (int i = 0; i < 4; i++) {
            int idx = tid + i * 512;        // 0..2047 = 64 rows x 32 kc4
            int r = idx & 63, kc4 = idx >> 6;
            float4 v = *(const float4*)(k_emb + (size_t)shq[r] * DKk + kc4 * 4);
            shAT[(kc4 * 4 + 0) * 68 + r] = v.x;
            shAT[(kc4 * 4 + 1) * 68 + r] = v.y;
            shAT[(kc4 * 4 + 2) * 68 + r] = v.z;
            shAT[(kc4 * 4 + 3) * 68 + r] = v.w;
        }
        __syncthreads();

        // col-packed: acc[row 2][colpair 2]
        u64 acc[2][2] = {};
#pragma unroll 8
        for (int kk = 0; kk < DKk; kk++) {
            float2 af = *(const float2*)(shAT + kk * 68 + rowb);
            ulonglong2 b = *(const ulonglong2*)(shBt + kk * 68 + c0);
            u64 a0 = pk2(af.x, af.x), a1 = pk2(af.y, af.y);
            acc[0][0] = fma2(a0, b.x, acc[0][0]);
            acc[0][1] = fma2(a0, b.y, acc[0][1]);
            acc[1][0] = fma2(a1, b.x, acc[1][0]);
            acc[1][1] = fma2(a1, b.y, acc[1][1]);
        }
        // softmax per row across 16 lanes (lane&15)
#pragma unroll
        for (int r = 0; r < 2; r++) {
            float2 v0 = up2(acc[r][0]), v1 = up2(acc[r][1]);
            float m = fmaxf(fmaxf(v0.x, v0.y), fmaxf(v1.x, v1.y));
#pragma unroll
            for (int o = 1; o < 16; o <<= 1)
                m = fmaxf(m, __shfl_xor_sync(0xffffffffu, m, o));
            float e0 = __expf(v0.x - m), e1 = __expf(v0.y - m);
            float e2 = __expf(v1.x - m), e3 = __expf(v1.y - m);
            float s = (e0 + e1) + (e2 + e3);
#pragma unroll
            for (int o = 1; o < 16; o <<= 1)
                s += __shfl_xor_sync(0xffffffffu, s, o);
            float inv = 1.0f / s;
            int row = t * 64 + rowb + r;
            *(float4*)(g_w + (size_t)row * DVv + c0) =
                make_float4(e0 * inv, e1 * inv, e2 * inv, e3 * inv);
        }
    }
}

// ---------------------------------------------------------------------------
// Kernel 2: e = sigmoid(v@eW+eb), a = tanh(v@aW+ab), fused. 512 thr, 64-row tiles.
// warp covers 8 rows x 64 cols per matrix:
//   rowblock = wid>>1, colhalf = wid&1
//   rowb = rowblock*8 + (lane>>4)*4, c0 = colhalf*64 + (lane&15)*4
// col-packed: A float4 + 4 movs, B ulonglong2 x2, 16 fma2
// ---------------------------------------------------------------------------
__global__ __launch_bounds__(512, 1)
void kern_ea(const int* __restrict__ qseq, const int* __restrict__ cseq,
             const float* __restrict__ v_emb,
             const float* __restrict__ eW, const float* __restrict__ eb,
             const float* __restrict__ aW, const float* __restrict__ ab) {
    extern __shared__ float sm[];
    float* shAT = sm;                    // [128 kk][68]
    float* shE  = sm + 128 * 68;         // [128][128]
    float* shAw = shE + 128 * 128;       // [128][128]
    float* shEb = shAw + 128 * 128;      // [128]
    float* shAb = shEb + 128;            // [128]
    __shared__ int shx[64];

    const int tid = threadIdx.x;
    const int lane = tid & 31;
    const int wid  = tid >> 5;

#pragma unroll
    for (int i = 0; i < 8; i++) {
        int idx = tid + i * 512;
        *(float4*)(shE  + idx * 4) = *(const float4*)(eW + idx * 4);
        *(float4*)(shAw + idx * 4) = *(const float4*)(aW + idx * 4);
    }
    if (tid < 128) { shEb[tid] = eb[tid]; shAb[tid] = ab[tid]; }

    const int rowb = (wid >> 1) * 8 + (lane >> 4) * 4;
    const int c0   = (wid & 1) * 64 + (lane & 15) * 4;

    for (int t = blockIdx.x; t < ROWS / 64; t += gridDim.x) {
        __syncthreads();
        if (tid < 64) {
            int row = t * 64 + tid;
            shx[tid] = qseq[row] + NQ * cseq[row];
        }
        __syncthreads();
#pragma unroll
        for (int i = 0; i < 4; i++) {
            int idx = tid + i * 512;        // 0..2047 = 64 rows x 32 kc4
            int r = idx & 63, kc4 = idx >> 6;
            float4 v = *(const float4*)(v_emb + (size_t)shx[r] * DKk + kc4 * 4);
            shAT[(kc4 * 4 + 0) * 68 + r] = v.x;
            shAT[(kc4 * 4 + 1) * 68 + r] = v.y;
            shAT[(kc4 * 4 + 2) * 68 + r] = v.z;
            shAT[(kc4 * 4 + 3) * 68 + r] = v.w;
        }
        __syncthreads();

        u64 ace[4][2] = {}, aca[4][2] = {};
#pragma unroll 4
        for (int kk = 0; kk < DKk; kk++) {
            float4 af = *(const float4*)(shAT + kk * 68 + rowb);
            ulonglong2 be = *(const ulonglong2*)(shE  + (kk << 7) + c0);
            ulonglong2 ba = *(const ulonglong2*)(shAw + (kk << 7) + c0);
            u64 a0 = pk2(af.x, af.x), a1 = pk2(af.y, af.y);
            u64 a2 = pk2(af.z, af.z), a3 = pk2(af.w, af.w);
            ace[0][0] = fma2(a0, be.x, ace[0][0]);
            ace[0][1] = fma2(a0, be.y, ace[0][1]);
            ace[1][0] = fma2(a1, be.x, ace[1][0]);
            ace[1][1] = fma2(a1, be.y, ace[1][1]);
            ace[2][0] = fma2(a2, be.x, ace[2][0]);
            ace[2][1] = fma2(a2, be.y, ace[2][1]);
            ace[3][0] = fma2(a3, be.x, ace[3][0]);
            ace[3][1] = fma2(a3, be.y, ace[3][1]);
            aca[0][0] = fma2(a0, ba.x, aca[0][0]);
            aca[0][1] = fma2(a0, ba.y, aca[0][1]);
            aca[1][0] = fma2(a1, ba.x, aca[1][0]);
            aca[1][1] = fma2(a1, ba.y, aca[1][1]);
            aca[2][0] = fma2(a2, ba.x, aca[2][0]);
            aca[2][1] = fma2(a2, ba.y, aca[2][1]);
            aca[3][0] = fma2(a3, ba.x, aca[3][0]);
            aca[3][1] = fma2(a3, ba.y, aca[3][1]);
        }
        float eb0 = shEb[c0], eb1 = shEb[c0+1], eb2 = shEb[c0+2], eb3 = shEb[c0+3];
        float ab0 = shAb[c0], ab1 = shAb[c0+1], ab2 = shAb[c0+2], ab3 = shAb[c0+3];
#pragma unroll
        for (int r = 0; r < 4; r++) {
            float2 e01 = up2(ace[r][0]), e23 = up2(ace[r][1]);
            float2 a01 = up2(aca[r][0]), a23 = up2(aca[r][1]);
            int row = t * 64 + rowb + r;
            *(float4*)(g_e + (size_t)row * DKk + c0) = make_float4(
                1.0f/(1.0f+__expf(-(e01.x+eb0))), 1.0f/(1.0f+__expf(-(e01.y+eb1))),
                1.0f/(1.0f+__expf(-(e23.x+eb2))), 1.0f/(1.0f+__expf(-(e23.y+eb3))));
            *(float4*)(g_a + (size_t)row * DKk + c0) = make_float4(
                tanha(a01.x+ab0), tanha(a01.y+ab1), tanha(a23.x+ab2), tanha(a23.y+ab3));
        }
    }
}

// ---------------------------------------------------------------------------
// Kernel 3: sequential scan, barrier-free. grid 128, 256 thr.
// Thread (j, h): j = wid*16 + (lane&15), h = lane>>4 owns v in [h*32, h*32+32).
// M positive; M += w*(a - e*M). Read combined via shfl_xor(16).
// ---------------------------------------------------------------------------
__global__ __launch_bounds__(256, 1)
void kern_scan(const float* __restrict__ Mv0) {
    const int b = blockIdx.x;
    const int tid = threadIdx.x;
    const int lane = tid & 31;
    const int wid  = tid >> 5;
    const int j  = wid * 16 + (lane & 15);
    const int h  = lane >> 4;
    const int vb = h * 32;

    u64 M[16];
#pragma unroll
    for (int p = 0; p < 16; p++)
        M[p] = pk2(Mv0[(vb + 2*p) * DKk + j], Mv0[(vb + 2*p + 1) * DKk + j]);

    const float* wp = g_w + (size_t)b * SS * DVv + vb;
    const float* ep = g_e + (size_t)b * SS * DKk + j;
    const float* ap = g_a + (size_t)b * SS * DKk + j;
    float* rp = g_reads + (size_t)b * SS * DKk + j;

    // prefetch step 0
    u64 wc[16];
#pragma unroll
    for (int q = 0; q < 8; q++) {
        ulonglong2 tld = *(const ulonglong2*)(wp + q * 4);
        wc[2*q] = tld.x; wc[2*q+1] = tld.y;
    }
    float ec = ep[0], ac = ap[0];

#pragma unroll 2
    for (int s = 0; s < SS; s++) {
        int sn = (s + 1 < SS) ? s + 1 : s;
        // prefetch next step
        u64 wn[16];
#pragma unroll
        for (int q = 0; q < 8; q++) {
            ulonglong2 tld = *(const ulonglong2*)(wp + sn * DVv + q * 4);
            wn[2*q] = tld.x; wn[2*q+1] = tld.y;
        }
        float en = ep[sn * DKk], an = ap[sn * DKk];

        u64 ne2 = pk2(-ec, -ec);
        u64 a2  = pk2(ac, ac);
        u64 rA = 0, rB = 0, rC = 0, rD = 0;
#pragma unroll
        for (int p = 0; p < 16; p += 4) {
            rA = fma2(wc[p],   M[p],   rA);
            M[p]   = fma2(wc[p],   fma2(M[p],   ne2, a2), M[p]);
            rB = fma2(wc[p+1], M[p+1], rB);
            M[p+1] = fma2(wc[p+1], fma2(M[p+1], ne2, a2), M[p+1]);
            rC = fma2(wc[p+2], M[p+2], rC);
            M[p+2] = fma2(wc[p+2], fma2(M[p+2], ne2, a2), M[p+2]);
            rD = fma2(wc[p+3], M[p+3], rD);
            M[p+3] = fma2(wc[p+3], fma2(M[p+3], ne2, a2), M[p+3]);
        }
        float2 fr = up2(add2(add2(rA, rB), add2(rC, rD)));
        float part = fr.x + fr.y;
        part += __shfl_xor_sync(0xffffffffu, part, 16);
        if (h == 0) rp[s * DKk] = part;

#pragma unroll
        for (int p = 0; p < 16; p++) wc[p] = wn[p];
        ec = en; ac = an;
    }
}

// ---------------------------------------------------------------------------
// Kernel 4: f = tanh([reads,k]@fW+fb); out = sigmoid(f@pW+pb). 512 thr, 64-row tiles.
// warp covers 4 rows x 128 cols: rowb = wid*4, c0 = lane*4. Col-packed acc[4][2].
// smem: shAT[256][68] + shB[256][128] + fb + pW = 201.7KB
// ---------------------------------------------------------------------------
__global__ __launch_bounds__(512, 1)
void kern_pred(const int* __restrict__ qseq,
               const float* __restrict__ k_emb,
               const float* __restrict__ fW, const float* __restrict__ fb,
               const float* __restrict__ pW, const float* __restrict__ pb,
               float* __restrict__ out) {
    extern __shared__ float sm[];
    float* shAT = sm;                    // [256 kk][68]
    float* shB  = sm + 256 * 68;         // [256][128]
    float* shfb = shB + 256 * 128;       // [128]
    float* shpW = shfb + 128;            // [128]
    __shared__ int shq[64];

    const int tid = threadIdx.x;
    const int lane = tid & 31;
    const int wid  = tid >> 5;

#pragma unroll
    for (int i = 0; i < 16; i++) {
        int idx = tid + i * 512;
        *(float4*)(shB + idx * 4) = *(const float4*)(fW + idx * 4);
    }
    if (tid < 128) { shfb[tid] = fb[tid]; shpW[tid] = pW[tid]; }
    const float pbv = pb[0];

    const int rowb = wid * 4;
    const int c0   = lane * 4;

    for (int t = blockIdx.x; t < ROWS / 64; t += gridDim.x) {
        __syncthreads();
        if (tid < 64) shq[tid] = qseq[t * 64 + tid];
        __syncthreads();
#pragma unroll
        for (int i = 0; i < 8; i++) {
            int idx = tid + i * 512;        // 0..4095 = 64 rows x 64 kc4
            int r = idx & 63, kc4 = idx >> 6;
            float4 v;
            if (kc4 < 32)
                v = *(const float4*)(g_reads + (size_t)(t * 64 + r) * DKk + kc4 * 4);
            else
                v = *(const float4*)(k_emb + (size_t)shq[r] * DKk + (kc4 - 32) * 4);
            shAT[(kc4 * 4 + 0) * 68 + r] = v.x;
            shAT[(kc4 * 4 + 1) * 68 + r] = v.y;
            shAT[(kc4 * 4 + 2) * 68 + r] = v.z;
            shAT[(kc4 * 4 + 3) * 68 + r] = v.w;
        }
        __syncthreads();

        u64 acc[4][2] = {};
#pragma unroll 8
        for (int kk = 0; kk < 256; kk++) {
            float4 af = *(const float4*)(shAT + kk * 68 + rowb);
            ulonglong2 bv = *(const ulonglong2*)(shB + (kk << 7) + c0);
            u64 a0 = pk2(af.x, af.x), a1 = pk2(af.y, af.y);
            u64 a2 = pk2(af.z, af.z), a3 = pk2(af.w, af.w);
            acc[0][0] = fma2(a0, bv.x, acc[0][0]);
            acc[0][1] = fma2(a0, bv.y, acc[0][1]);
            acc[1][0] = fma2(a1, bv.x, acc[1][0]);
            acc[1][1] = fma2(a1, bv.y, acc[1][1]);
            acc[2][0] = fma2(a2, bv.x, acc[2][0]);
            acc[2][1] = fma2(a2, bv.y, acc[2][1]);
            acc[3][0] = fma2(a3, bv.x, acc[3][0]);
            acc[3][1] = fma2(a3, bv.y, acc[3][1]);
        }
        float fb0 = shfb[c0], fb1 = shfb[c0+1], fb2 = shfb[c0+2], fb3 = shfb[c0+3];
        float pw0 = shpW[c0], pw1 = shpW[c0+1], pw2 = shpW[c0+2], pw3 = shpW[c0+3];
#pragma unroll
        for (int r = 0; r < 4; r++) {
            float2 v01 = up2(acc[r][0]), v23 = up2(acc[r][1]);
            float p = tanha(v01.x + fb0) * pw0;
            p = fmaf(tanha(v01.y + fb1), pw1, p);
            p = fmaf(tanha(v23.x + fb2), pw2, p);
            p = fmaf(tanha(v23.y + fb3), pw3, p);
#pragma unroll
            for (int o = 1; o < 32; o <<= 1)
                p += __shfl_xor_sync(0xffffffffu, p, o);
            if (lane == 0)
                out[t * 64 + rowb + r] = 1.0f / (1.0f + __expf(-(p + pbv)));
        }
    }
}

// ---------------------------------------------------------------------------
extern "C" void kernel_launch(void* const* d_in, const int* in_sizes, int n_in,
                              void* d_out, int out_size) {
    (void)in_sizes; (void)n_in; (void)out_size;
    const int*   qseq  = (const int*)d_in[0];
    const int*   cseq  = (const int*)d_in[1];
    const float* k_emb = (const float*)d_in[2];
    const float* v_emb = (const float*)d_in[3];
    const float* Mk    = (const float*)d_in[4];
    const float* Mv0   = (const float*)d_in[5];
    const float* fW    = (const float*)d_in[6];
    const float* fb    = (const float*)d_in[7];
    const float* eW    = (const float*)d_in[8];
    const float* eb    = (const float*)d_in[9];
    const float* aW    = (const float*)d_in[10];
    const float* ab    = (const float*)d_in[11];
    const float* pW    = (const float*)d_in[12];
    const float* pb    = (const float*)d_in[13];
    float* out = (float*)d_out;

    const int smw  = (128*68 * 2) * 4;                         // 69632
    const int smea = (128*68 + 2*128*128 + 256) * 4;           // 166912
    const int smp  = (256*68 + 256*128 + 256) * 4;             // 201728

    cudaFuncSetAttribute(kern_w,    cudaFuncAttributeMaxDynamicSharedMemorySize, smw);
    cudaFuncSetAttribute(kern_ea,   cudaFuncAttributeMaxDynamicSharedMemorySize, smea);
    cudaFuncSetAttribute(kern_pred, cudaFuncAttributeMaxDynamicSharedMemorySize, smp);

    kern_w   <<<148, 512, smw>>>(qseq, k_emb, Mk);
    kern_ea  <<<148, 512, smea>>>(qseq, cseq, v_emb, eW, eb, aW, ab);
    kern_scan<<<128, 256>>>(Mv0);
    kern_pred<<<148, 512, smp>>>(qseq, k_emb, fW, fb, pW, pb, out);
}

// round 9
// speedup vs baseline: 1.8907x; 1.0315x over previous
#include <cuda_runtime.h>

#define NQ 10000
#define BB 128
#define SS 200
#define DKk 128
#define DVv 64
#define ROWS (BB*SS)     // 25600

typedef unsigned long long u64;

__device__ __forceinline__ u64 pk2(float lo, float hi) {
    u64 r; asm("mov.b64 %0,{%1,%2};" : "=l"(r) : "f"(lo), "f"(hi)); return r;
}
__device__ __forceinline__ float2 up2(u64 a) {
    float2 v; asm("mov.b64 {%0,%1},%2;" : "=f"(v.x), "=f"(v.y) : "l"(a)); return v;
}
__device__ __forceinline__ u64 fma2(u64 a, u64 b, u64 c) {
    u64 d; asm("fma.rn.f32x2 %0,%1,%2,%3;" : "=l"(d) : "l"(a), "l"(b), "l"(c)); return d;
}
__device__ __forceinline__ u64 add2(u64 a, u64 b) {
    u64 d; asm("add.rn.f32x2 %0,%1,%2;" : "=l"(d) : "l"(a), "l"(b)); return d;
}
__device__ __forceinline__ float tanha(float x) {
    float y; asm("tanh.approx.f32 %0,%1;" : "=f"(y) : "f"(x)); return y;
}

// Scratch
__device__ float g_w[ROWS*DVv];
__device__ float g_e[ROWS*DKk];
__device__ float g_a[ROWS*DKk];
__device__ float g_reads[ROWS*DKk];

// ---------------------------------------------------------------------------
// Kernel 1: w = softmax(k_emb[q] @ Mk^T). 256-row tiles, grid 100 (ONE wave).
// smem: shAT[128 kk][264] + shBt[128 kk][68] = 166KB
// warp: 16 rows (8 rowpairs) x 64 cols; lane: 2 cols. rowb=wid*16, c0=lane*2.
// wf/kk/SM = 16*(4+2)=96 < fma2 floor 128 cyc.
// ---------------------------------------------------------------------------
__global__ __launch_bounds__(512, 1)
void kern_w(const int* __restrict__ qseq,
            const float* __restrict__ k_emb,
            const float* __restrict__ Mk) {
    extern __shared__ float sm[];
    float* shAT = sm;               // [128][264]
    float* shBt = sm + 128 * 264;   // [128][68]
    __shared__ int shq[256];

    const int tid = threadIdx.x;
    const int lane = tid & 31;
    const int wid  = tid >> 5;

    // Stage Mk^T once: Mk[col][kk] -> shBt[kk][col]
#pragma unroll
    for (int i = 0; i < 4; i++) {
        int idx = tid + i * 512;            // 0..2047 = 64 cols x 32 kc4
        int col = idx & 63, kc4 = idx >> 6;
        float4 v = *(const float4*)(Mk + col * DKk + kc4 * 4);
        shBt[(kc4 * 4 + 0) * 68 + col] = v.x;
        shBt[(kc4 * 4 + 1) * 68 + col] = v.y;
        shBt[(kc4 * 4 + 2) * 68 + col] = v.z;
        shBt[(kc4 * 4 + 3) * 68 + col] = v.w;
    }

    const int rowb = wid * 16;
    const int c0   = lane * 2;

    for (int t = blockIdx.x; t < ROWS / 256; t += gridDim.x) {
        __syncthreads();
        if (tid < 256) shq[tid] = qseq[t * 256 + tid];
        __syncthreads();
#pragma unroll
        for (int i = 0; i < 16; i++) {
            int idx = tid + i * 512;        // 0..8191 = 256 rows x 32 kc4
            int r = idx & 255, kc4 = idx >> 8;
            float4 v = *(const float4*)(k_emb + (size_t)shq[r] * DKk + kc4 * 4);
            shAT[(kc4 * 4 + 0) * 264 + r] = v.x;
            shAT[(kc4 * 4 + 1) * 264 + r] = v.y;
            shAT[(kc4 * 4 + 2) * 264 + r] = v.z;
            shAT[(kc4 * 4 + 3) * 264 + r] = v.w;
        }
        __syncthreads();

        u64 acc[8][2] = {};
#pragma unroll 4
        for (int kk = 0; kk < DKk; kk++) {
            const float* ab = shAT + kk * 264 + rowb;
            ulonglong2 a01 = *(const ulonglong2*)(ab);
            ulonglong2 a23 = *(const ulonglong2*)(ab + 4);
            ulonglong2 a45 = *(const ulonglong2*)(ab + 8);
            ulonglong2 a67 = *(const ulonglong2*)(ab + 12);
            float2 bf = *(const float2*)(shBt + kk * 68 + c0);
            u64 b0 = pk2(bf.x, bf.x), b1 = pk2(bf.y, bf.y);
            acc[0][0] = fma2(a01.x, b0, acc[0][0]);
            acc[0][1] = fma2(a01.x, b1, acc[0][1]);
            acc[1][0] = fma2(a01.y, b0, acc[1][0]);
            acc[1][1] = fma2(a01.y, b1, acc[1][1]);
            acc[2][0] = fma2(a23.x, b0, acc[2][0]);
            acc[2][1] = fma2(a23.x, b1, acc[2][1]);
            acc[3][0] = fma2(a23.y, b0, acc[3][0]);
            acc[3][1] = fma2(a23.y, b1, acc[3][1]);
            acc[4][0] = fma2(a45.x, b0, acc[4][0]);
            acc[4][1] = fma2(a45.x, b1, acc[4][1]);
            acc[5][0] = fma2(a45.y, b0, acc[5][0]);
            acc[5][1] = fma2(a45.y, b1, acc[5][1]);
            acc[6][0] = fma2(a67.x, b0, acc[6][0]);
            acc[6][1] = fma2(a67.x, b1, acc[6][1]);
            acc[7][0] = fma2(a67.y, b0, acc[7][0]);
            acc[7][1] = fma2(a67.y, b1, acc[7][1]);
        }
        // softmax per row across full warp (64 cols = 32 lanes x 2)
#pragma unroll
        for (int rp = 0; rp < 8; rp++) {
            float2 v0 = up2(acc[rp][0]), v1 = up2(acc[rp][1]);
            float mlo = fmaxf(v0.x, v1.x);
            float mhi = fmaxf(v0.y, v1.y);
#pragma unroll
            for (int o = 1; o < 32; o <<= 1) {
                mlo = fmaxf(mlo, __shfl_xor_sync(0xffffffffu, mlo, o));
                mhi = fmaxf(mhi, __shfl_xor_sync(0xffffffffu, mhi, o));
            }
            float l0 = __expf(v0.x - mlo), l1 = __expf(v1.x - mlo);
            float h0 = __expf(v0.y - mhi), h1 = __expf(v1.y - mhi);
            float slo = l0 + l1, shi = h0 + h1;
#pragma unroll
            for (int o = 1; o < 32; o <<= 1) {
                slo += __shfl_xor_sync(0xffffffffu, slo, o);
                shi += __shfl_xor_sync(0xffffffffu, shi, o);
            }
            float ilo = 1.0f / slo, ihi = 1.0f / shi;
            int row = t * 256 + rowb + 2 * rp;
            *(float2*)(g_w + (size_t)row * DVv + c0) = make_float2(l0 * ilo, l1 * ilo);
            *(float2*)(g_w + (size_t)(row + 1) * DVv + c0) = make_float2(h0 * ihi, h1 * ihi);
        }
    }
}

// ---------------------------------------------------------------------------
// Kernel 2: e = sigmoid(v@eW+eb), a = tanh(v@aW+ab). 64-row tiles (400), grid 148.
// Warps split by MATRIX: warps 0-7 -> eW, 8-15 -> aW. Each warp 8 rows x 128 cols.
// smem: shAT[128][68] + shE[128][128] + shAw[128][128] + biases = 163KB
// wf/kk/SM = 16*(2+4) = 96 < 128.
// ---------------------------------------------------------------------------
__global__ __launch_bounds__(512, 1)
void kern_ea(const int* __restrict__ qseq, const int* __restrict__ cseq,
             const float* __restrict__ v_emb,
             const float* __restrict__ eW, const float* __restrict__ eb,
             const float* __restrict__ aW, const float* __restrict__ ab) {
    extern __shared__ float sm[];
    float* shAT = sm;                    // [128][68]
    float* shE  = sm + 128 * 68;         // [128][128]
    float* shAw = shE + 128 * 128;       // [128][128]
    float* shEb = shAw + 128 * 128;      // [128]
    float* shAb = shEb + 128;            // [128]
    __shared__ int shx[64];

    const int tid = threadIdx.x;
    const int lane = tid & 31;
    const int wid  = tid >> 5;

#pragma unroll
    for (int i = 0; i < 8; i++) {
        int idx = tid + i * 512;
        *(float4*)(shE  + idx * 4) = *(const float4*)(eW + idx * 4);
        *(float4*)(shAw + idx * 4) = *(const float4*)(aW + idx * 4);
    }
    if (tid < 128) { shEb[tid] = eb[tid]; shAb[tid] = ab[tid]; }

    const int mat  = wid >> 3;           // 0 = e, 1 = a
    const int rowb = (wid & 7) * 8;
    const int c0   = lane * 4;
    const float* W = mat ? shAw : shE;

    for (int t = blockIdx.x; t < ROWS / 64; t += gridDim.x) {
        __syncthreads();
        if (tid < 64) {
            int row = t * 64 + tid;
            shx[tid] = qseq[row] + NQ * cseq[row];
        }
        __syncthreads();
#pragma unroll
        for (int i = 0; i < 4; i++) {
            int idx = tid + i * 512;        // 0..2047 = 64 rows x 32 kc4
            int r = idx & 63, kc4 = idx >> 6;
            float4 v = *(const float4*)(v_emb + (size_t)shx[r] * DKk + kc4 * 4);
            shAT[(kc4 * 4 + 0) * 68 + r] = v.x;
            shAT[(kc4 * 4 + 1) * 68 + r] = v.y;
            shAT[(kc4 * 4 + 2) * 68 + r] = v.z;
            shAT[(kc4 * 4 + 3) * 68 + r] = v.w;
        }
        __syncthreads();

        u64 acc[4][4] = {};
#pragma unroll 4
        for (int kk = 0; kk < DKk; kk++) {
            const float* abp = shAT + kk * 68 + rowb;
            ulonglong2 aA = *(const ulonglong2*)(abp);
            ulonglong2 aB = *(const ulonglong2*)(abp + 4);
            float4 bf = *(const float4*)(W + (kk << 7) + c0);
            u64 b0 = pk2(bf.x, bf.x), b1 = pk2(bf.y, bf.y);
            u64 b2 = pk2(bf.z, bf.z), b3 = pk2(bf.w, bf.w);
            acc[0][0] = fma2(aA.x, b0, acc[0][0]);
            acc[0][1] = fma2(aA.x, b1, acc[0][1]);
            acc[0][2] = fma2(aA.x, b2, acc[0][2]);
            acc[0][3] = fma2(aA.x, b3, acc[0][3]);
            acc[1][0] = fma2(aA.y, b0, acc[1][0]);
            acc[1][1] = fma2(aA.y, b1, acc[1][1]);
            acc[1][2] = fma2(aA.y, b2, acc[1][2]);
            acc[1][3] = fma2(aA.y, b3, acc[1][3]);
            acc[2][0] = fma2(aB.x, b0, acc[2][0]);
            acc[2][1] = fma2(aB.x, b1, acc[2][1]);
            acc[2][2] = fma2(aB.x, b2, acc[2][2]);
            acc[2][3] = fma2(aB.x, b3, acc[2][3]);
            acc[3][0] = fma2(aB.y, b0, acc[3][0]);
            acc[3][1] = fma2(aB.y, b1, acc[3][1]);
            acc[3][2] = fma2(aB.y, b2, acc[3][2]);
            acc[3][3] = fma2(aB.y, b3, acc[3][3]);
        }
        const float* bias = mat ? shAb : shEb;
        float b0 = bias[c0], b1 = bias[c0+1], b2 = bias[c0+2], b3 = bias[c0+3];
        float* outbuf = mat ? g_a : g_e;
#pragma unroll
        for (int rp = 0; rp < 4; rp++) {
            float2 v0 = up2(acc[rp][0]), v1 = up2(acc[rp][1]);
            float2 v2 = up2(acc[rp][2]), v3 = up2(acc[rp][3]);
            int row = t * 64 + rowb + 2 * rp;
            float4 olo, ohi;
            if (mat) {
                olo = make_float4(tanha(v0.x+b0), tanha(v1.x+b1), tanha(v2.x+b2), tanha(v3.x+b3));
                ohi = make_float4(tanha(v0.y+b0), tanha(v1.y+b1), tanha(v2.y+b2), tanha(v3.y+b3));
            } else {
                olo = make_float4(1.0f/(1.0f+__expf(-(v0.x+b0))), 1.0f/(1.0f+__expf(-(v1.x+b1))),
                                  1.0f/(1.0f+__expf(-(v2.x+b2))), 1.0f/(1.0f+__expf(-(v3.x+b3))));
                ohi = make_float4(1.0f/(1.0f+__expf(-(v0.y+b0))), 1.0f/(1.0f+__expf(-(v1.y+b1))),
                                  1.0f/(1.0f+__expf(-(v2.y+b2))), 1.0f/(1.0f+__expf(-(v3.y+b3))));
            }
            *(float4*)(outbuf + (size_t)row * DKk + c0) = olo;
            *(float4*)(outbuf + (size_t)(row + 1) * DKk + c0) = ohi;
        }
    }
}

// ---------------------------------------------------------------------------
// Kernel 3: sequential scan, barrier-free.
// ---------------------------------------------------------------------------
__global__ __launch_bounds__(256, 1)
void kern_scan(const float* __restrict__ Mv0) {
    const int b = blockIdx.x;
    const int tid = threadIdx.x;
    const int lane = tid & 31;
    const int wid  = tid >> 5;
    const int j  = wid * 16 + (lane & 15);
    const int h  = lane >> 4;
    const int vb = h * 32;

    u64 M[16];
#pragma unroll
    for (int p = 0; p < 16; p++)
        M[p] = pk2(Mv0[(vb + 2*p) * DKk + j], Mv0[(vb + 2*p + 1) * DKk + j]);

    const float* wp = g_w + (size_t)b * SS * DVv + vb;
    const float* ep = g_e + (size_t)b * SS * DKk + j;
    const float* ap = g_a + (size_t)b * SS * DKk + j;
    float* rp = g_reads + (size_t)b * SS * DKk + j;

    u64 wc[16];
#pragma unroll
    for (int q = 0; q < 8; q++) {
        ulonglong2 tld = *(const ulonglong2*)(wp + q * 4);
        wc[2*q] = tld.x; wc[2*q+1] = tld.y;
    }
    float ec = ep[0], ac = ap[0];

#pragma unroll 2
    for (int s = 0; s < SS; s++) {
        int sn = (s + 1 < SS) ? s + 1 : s;
        u64 wn[16];
#pragma unroll
        for (int q = 0; q < 8; q++) {
            ulonglong2 tld = *(const ulonglong2*)(wp + sn * DVv + q * 4);
            wn[2*q] = tld.x; wn[2*q+1] = tld.y;
        }
        float en = ep[sn * DKk], an = ap[sn * DKk];

        u64 ne2 = pk2(-ec, -ec);
        u64 a2  = pk2(ac, ac);
        u64 rA = 0, rB = 0, rC = 0, rD = 0;
#pragma unroll
        for (int p = 0; p < 16; p += 4) {
            rA = fma2(wc[p],   M[p],   rA);
            M[p]   = fma2(wc[p],   fma2(M[p],   ne2, a2), M[p]);
            rB = fma2(wc[p+1], M[p+1], rB);
            M[p+1] = fma2(wc[p+1], fma2(M[p+1], ne2, a2), M[p+1]);
            rC = fma2(wc[p+2], M[p+2], rC);
            M[p+2] = fma2(wc[p+2], fma2(M[p+2], ne2, a2), M[p+2]);
            rD = fma2(wc[p+3], M[p+3], rD);
            M[p+3] = fma2(wc[p+3], fma2(M[p+3], ne2, a2), M[p+3]);
        }
        float2 fr = up2(add2(add2(rA, rB), add2(rC, rD)));
        float part = fr.x + fr.y;
        part += __shfl_xor_sync(0xffffffffu, part, 16);
        if (h == 0) rp[s * DKk] = part;

#pragma unroll
        for (int p = 0; p < 16; p++) wc[p] = wn[p];
        ec = en; ac = an;
    }
}

// ---------------------------------------------------------------------------
// Kernel 4: f = tanh([reads,k]@fW+fb); out = sigmoid(f@pW+pb).
// 64-row tiles (400), grid 148. Warps split by K-HALF:
//   warps 0-7: K 0..127 (reads), warps 8-15: K 128..255 (k_emb).
// Each warp 8 rows x 128 cols. Partials combined via smem.
// smem: shAT[256][68] + shB[256][128] + biases = 197KB
// wf/kk/SM = 16*(2+4) = 96 < 128.
// ---------------------------------------------------------------------------
__global__ __launch_bounds__(512, 1)
void kern_pred(const int* __restrict__ qseq,
               const float* __restrict__ k_emb,
               const float* __restrict__ fW, const float* __restrict__ fb,
               const float* __restrict__ pW, const float* __restrict__ pb,
               float* __restrict__ out) {
    extern __shared__ float sm[];
    float* shAT = sm;                    // [256 kk][68]
    float* shB  = sm + 256 * 68;         // [256][128]
    float* shfb = shB + 256 * 128;       // [128]
    float* shpW = shfb + 128;            // [128]
    __shared__ int shq[64];

    const int tid = threadIdx.x;
    const int lane = tid & 31;
    const int wid  = tid >> 5;

#pragma unroll
    for (int i = 0; i < 16; i++) {
        int idx = tid + i * 512;
        *(float4*)(shB + idx * 4) = *(const float4*)(fW + idx * 4);
    }
    if (tid < 128) { shfb[tid] = fb[tid]; shpW[tid] = pW[tid]; }
    const float pbv = pb[0];

    const int khalf = wid >> 3;
    const int rowb  = (wid & 7) * 8;
    const int c0    = lane * 4;
    const int kbase = khalf * 128;

    for (int t = blockIdx.x; t < ROWS / 64; t += gridDim.x) {
        __syncthreads();   // protects shq + reduction buffer from prev tile
        if (tid < 64) shq[tid] = qseq[t * 64 + tid];
        __syncthreads();
#pragma unroll
        for (int i = 0; i < 8; i++) {
            int idx = tid + i * 512;        // 0..4095 = 64 rows x 64 kc4
            int r = idx & 63, kc4 = idx >> 6;
            float4 v;
            if (kc4 < 32)
                v = *(const float4*)(g_reads + (size_t)(t * 64 + r) * DKk + kc4 * 4);
            else
                v = *(const float4*)(k_emb + (size_t)shq[r] * DKk + (kc4 - 32) * 4);
            shAT[(kc4 * 4 + 0) * 68 + r] = v.x;
            shAT[(kc4 * 4 + 1) * 68 + r] = v.y;
            shAT[(kc4 * 4 + 2) * 68 + r] = v.z;
            shAT[(kc4 * 4 + 3) * 68 + r] = v.w;
        }
        __syncthreads();

        u64 acc[4][4] = {};
#pragma unroll 4
        for (int kk = 0; kk < 128; kk++) {
            int kki = kbase + kk;
            const float* abp = shAT + kki * 68 + rowb;
            ulonglong2 aA = *(const ulonglong2*)(abp);
            ulonglong2 aB = *(const ulonglong2*)(abp + 4);
            float4 bf = *(const float4*)(shB + (kki << 7) + c0);
            u64 b0 = pk2(bf.x, bf.x), b1 = pk2(bf.y, bf.y);
            u64 b2 = pk2(bf.z, bf.z), b3 = pk2(bf.w, bf.w);
            acc[0][0] = fma2(aA.x, b0, acc[0][0]);
            acc[0][1] = fma2(aA.x, b1, acc[0][1]);
            acc[0][2] = fma2(aA.x, b2, acc[0][2]);
            acc[0][3] = fma2(aA.x, b3, acc[0][3]);
            acc[1][0] = fma2(aA.y, b0, acc[1][0]);
            acc[1][1] = fma2(aA.y, b1, acc[1][1]);
            acc[1][2] = fma2(aA.y, b2, acc[1][2]);
            acc[1][3] = fma2(aA.y, b3, acc[1][3]);
            acc[2][0] = fma2(aB.x, b0, acc[2][0]);
            acc[2][1] = fma2(aB.x, b1, acc[2][1]);
            acc[2][2] = fma2(aB.x, b2, acc[2][2]);
            acc[2][3] = fma2(aB.x, b3, acc[2][3]);
            acc[3][0] = fma2(aB.y, b0, acc[3][0]);
            acc[3][1] = fma2(aB.y, b1, acc[3][1]);
            acc[3][2] = fma2(aB.y, b2, acc[3][2]);
            acc[3][3] = fma2(aB.y, b3, acc[3][3]);
        }

        // combine K-halves: warps 8-15 dump partials into smem (over shAT)
        __syncthreads();
        u64* shRed = (u64*)shAT;   // [8 rowg][32 lane][16]
        if (khalf == 1) {
            u64* dst = shRed + ((size_t)(wid & 7) * 32 + lane) * 16;
#pragma unroll
            for (int rp = 0; rp < 4; rp++)
#pragma unroll
                for (int c = 0; c < 4; c++) dst[rp * 4 + c] = acc[rp][c];
        }
        __syncthreads();
        if (khalf == 0) {
            const u64* src = shRed + ((size_t)(wid & 7) * 32 + lane) * 16;
#pragma unroll
            for (int rp = 0; rp < 4; rp++)
#pragma unroll
                for (int c = 0; c < 4; c++) acc[rp][c] = add2(acc[rp][c], src[rp * 4 + c]);

            float f0 = shfb[c0], f1 = shfb[c0+1], f2 = shfb[c0+2], f3 = shfb[c0+3];
            float p0 = shpW[c0], p1 = shpW[c0+1], p2 = shpW[c0+2], p3 = shpW[c0+3];
#pragma unroll
            for (int rp = 0; rp < 4; rp++) {
                float2 v0 = up2(acc[rp][0]), v1 = up2(acc[rp][1]);
                float2 v2 = up2(acc[rp][2]), v3 = up2(acc[rp][3]);
                float plo = tanha(v0.x + f0) * p0;
                plo = fmaf(tanha(v1.x + f1), p1, plo);
                plo = fmaf(tanha(v2.x + f2), p2, plo);
                plo = fmaf(tanha(v3.x + f3), p3, plo);
                float phi = tanha(v0.y + f0) * p0;
                phi = fmaf(tanha(v1.y + f1), p1, phi);
                phi = fmaf(tanha(v2.y + f2), p2, phi);
                phi = fmaf(tanha(v3.y + f3), p3, phi);
#pragma unroll
                for (int o = 1; o < 32; o <<= 1) {
                    plo += __shfl_xor_sync(0xffffffffu, plo, o);
                    phi += __shfl_xor_sync(0xffffffffu, phi, o);
                }
                if (lane == 0) {
                    int row = t * 64 + rowb + 2 * rp;
                    out[row]     = 1.0f / (1.0f + __expf(-(plo + pbv)));
                    out[row + 1] = 1.0f / (1.0f + __expf(-(phi + pbv)));
                }
            }
        }
    }
}

// ---------------------------------------------------------------------------
extern "C" void kernel_launch(void* const* d_in, const int* in_sizes, int n_in,
                              void* d_out, int out_size) {
    (void)in_sizes; (void)n_in; (void)out_size;
    const int*   qseq  = (const int*)d_in[0];
    const int*   cseq  = (const int*)d_in[1];
    const float* k_emb = (const float*)d_in[2];
    const float* v_emb = (const float*)d_in[3];
    const float* Mk    = (const float*)d_in[4];
    const float* Mv0   = (const float*)d_in[5];
    const float* fW    = (const float*)d_in[6];
    const float* fb    = (const float*)d_in[7];
    const float* eW    = (const float*)d_in[8];
    const float* eb    = (const float*)d_in[9];
    const float* aW    = (const float*)d_in[10];
    const float* ab    = (const float*)d_in[11];
    const float* pW    = (const float*)d_in[12];
    const float* pb    = (const float*)d_in[13];
    float* out = (float*)d_out;

    const int smw  = (128*264 + 128*68) * 4;                   // 169984
    const int smea = (128*68 + 2*128*128 + 256) * 4;           // 166912
    const int smp  = (256*68 + 256*128 + 256) * 4;             // 201728

    cudaFuncSetAttribute(kern_w,    cudaFuncAttributeMaxDynamicSharedMemorySize, smw);
    cudaFuncSetAttribute(kern_ea,   cudaFuncAttributeMaxDynamicSharedMemorySize, smea);
    cudaFuncSetAttribute(kern_pred, cudaFuncAttributeMaxDynamicSharedMemorySize, smp);

    kern_w   <<<100, 512, smw>>>(qseq, k_emb, Mk);
    kern_ea  <<<148, 512, smea>>>(qseq, cseq, v_emb, eW, eb, aW, ab);
    kern_scan<<<128, 256>>>(Mv0);
    kern_pred<<<148, 512, smp>>>(qseq, k_emb, fW, fb, pW, pb, out);
}